// round 13
// baseline (speedup 1.0000x reference)
#include <cuda_runtime.h>
#include <cuda_bf16.h>
#include <cstdint>

#define SEQ_L 2048
#define DIM 1024
#define NHEAD 16
#define DHEAD 64
#define BATCH 2

// Scratch (allocation-free)
__device__ float g_Xr[3 * BATCH * SEQ_L * DIM];        // tf32-rounded q,k,v inputs
__device__ float g_Q[BATCH * NHEAD * SEQ_L * DHEAD];
__device__ __nv_bfloat16 g_Kh16[BATCH * NHEAD * SEQ_L * DHEAD];  // K hi (bf16)
__device__ __nv_bfloat16 g_Kl16[BATCH * NHEAD * SEQ_L * DHEAD];  // K lo (bf16)
__device__ float g_Vt[BATCH * NHEAD * DHEAD * SEQ_L]; // V^T [B,H,DH,L], tf32-rounded
__device__ float g_O[BATCH * SEQ_L * DIM];            // tf32-rounded attention out
__device__ float g_Wt[4 * DIM * DIM];                 // W^T, tf32-rounded

// ---------------------------------------------------------------------------
__device__ __forceinline__ unsigned smem_u32(const void* p) {
    unsigned a;
    asm("{ .reg .u64 t; cvta.to.shared.u64 t, %1; cvt.u32.u64 %0, t; }"
        : "=r"(a) : "l"(p));
    return a;
}
__device__ __forceinline__ unsigned f2tf32(float f) {
    unsigned u;
    asm("cvt.rna.tf32.f32 %0, %1;" : "=r"(u) : "f"(f));
    return u;
}
__device__ __forceinline__ float uif(unsigned u) { return __uint_as_float(u); }
__device__ __forceinline__ float ex2(float x) {
    float y;
    asm("ex2.approx.f32 %0, %1;" : "=f"(y) : "f"(x));
    return y;
}

__device__ __forceinline__ void mma_tf32(float* c, const unsigned* a, const unsigned* b) {
    asm volatile(
        "mma.sync.aligned.m16n8k8.row.col.f32.tf32.tf32.f32 "
        "{%0,%1,%2,%3}, {%4,%5,%6,%7}, {%8,%9}, {%0,%1,%2,%3};"
        : "+f"(c[0]), "+f"(c[1]), "+f"(c[2]), "+f"(c[3])
        : "r"(a[0]), "r"(a[1]), "r"(a[2]), "r"(a[3]), "r"(b[0]), "r"(b[1]));
}
__device__ __forceinline__ void mma_bf16(float* c, const unsigned* a, unsigned b) {
    asm volatile(
        "mma.sync.aligned.m16n8k8.row.col.f32.bf16.bf16.f32 "
        "{%0,%1,%2,%3}, {%4,%5}, {%6}, {%0,%1,%2,%3};"
        : "+f"(c[0]), "+f"(c[1]), "+f"(c[2]), "+f"(c[3])
        : "r"(a[0]), "r"(a[1]), "r"(b));
}
__device__ __forceinline__ void ldsm4(unsigned* r, unsigned addr) {
    asm volatile("ldmatrix.sync.aligned.m8n8.x4.shared.b16 {%0,%1,%2,%3}, [%4];"
        : "=r"(r[0]), "=r"(r[1]), "=r"(r[2]), "=r"(r[3]) : "r"(addr));
}

// ---------------------------------------------------------------------------
// Prepass: round q,k,v inputs to tf32 into g_Xr
// ---------------------------------------------------------------------------
__global__ __launch_bounds__(256) void round_inputs(
    const float* __restrict__ q, const float* __restrict__ k,
    const float* __restrict__ v, float* __restrict__ out)
{
    const int z = blockIdx.y;
    const float* src = (z == 0) ? q : (z == 1) ? k : v;
    size_t i = ((size_t)blockIdx.x * 256 + threadIdx.x) * 4;
    float4 a = *(const float4*)(src + i);
    a.x = uif(f2tf32(a.x)); a.y = uif(f2tf32(a.y));
    a.z = uif(f2tf32(a.z)); a.w = uif(f2tf32(a.w));
    *(float4*)(out + (size_t)z * (BATCH * SEQ_L * DIM) + i) = a;
}

// ---------------------------------------------------------------------------
// Batched transpose + tf32 pre-round: g_Wt[z] = round_tf32(W_z^T)
// ---------------------------------------------------------------------------
__global__ __launch_bounds__(256) void transpose4(
    const float* __restrict__ w0, const float* __restrict__ w1,
    const float* __restrict__ w2, const float* __restrict__ w3,
    float* __restrict__ out)
{
    __shared__ float tile[32][33];
    const float* in = (blockIdx.z == 0) ? w0 : (blockIdx.z == 1) ? w1
                    : (blockIdx.z == 2) ? w2 : w3;
    float* o = out + (size_t)blockIdx.z * DIM * DIM;
    const int x = blockIdx.x * 32;
    const int y = blockIdx.y * 32;
    const int tx = threadIdx.x, ty = threadIdx.y;
#pragma unroll
    for (int i = 0; i < 32; i += 8)
        tile[ty + i][tx] = in[(size_t)(y + ty + i) * DIM + x + tx];
    __syncthreads();
#pragma unroll
    for (int i = 0; i < 32; i += 8)
        o[(size_t)(x + ty + i) * DIM + y + tx] = uif(f2tf32(tile[tx][ty + i]));
}

// ---------------------------------------------------------------------------
// tf32 mma.sync GEMM, ldmatrix fragments, pre-rounded A and B.
// CTA 128x128, BK=32, 256 threads = 8 warps of 64x32 tiles.
// 3-stage cp.async pipeline, ONE __syncthreads per chunk.
// remap: 0 row-major; 1 [B,H,L,DH]; 2 [B,H,DH,L] rounded; 3 bf16 hi/lo K
// ---------------------------------------------------------------------------
#define BK 32
#define GSTG 18432u                       // bytes per stage per operand
#define GSMEM (3 * 2 * 18432)             // 110592 bytes

struct GemmArgs {
    const float* X[3];
    const float* Wt[3];
    const float* bias[3];
    float* out[3];
    float* out2[3];
    int remap[3];
};

__global__ __launch_bounds__(256, 2) void gemm_mma(GemmArgs ga)
{
    extern __shared__ float gsm[];
    const int z = blockIdx.z;
    const float* __restrict__ X = ga.X[z];
    const float* __restrict__ Wt = ga.Wt[z];
    const float* __restrict__ bias = ga.bias[z];
    float* __restrict__ out = ga.out[z];
    float* __restrict__ out2 = ga.out2[z];
    const int remap = ga.remap[z];

    const int tid = threadIdx.x;
    const int wid = tid >> 5, lid = tid & 31;
    const int wm = wid >> 2;        // 0..1 (64-row band)
    const int wn = wid & 3;         // 0..3 (32-col band)
    const int g = lid >> 2;
    const int t = lid & 3;
    const int bm = blockIdx.y * 128;
    const int bn = blockIdx.x * 128;

    const unsigned uA = smem_u32(gsm);
    const unsigned uB = uA + 3 * GSTG;

    const int mi = lid >> 3, ri = lid & 7;
    const unsigned aoff0 = ((unsigned)((wm * 64 + ((mi & 1) << 3) + ri) * 36
                                       + ((mi >> 1) << 2))) << 2;
    const unsigned boff0 = ((unsigned)((wn * 32 + ((mi >> 1) << 3) + ri) * 36
                                       + ((mi & 1) << 2))) << 2;

    float acc[4][4][4];
#pragma unroll
    for (int mf = 0; mf < 4; mf++)
#pragma unroll
        for (int nf = 0; nf < 4; nf++)
#pragma unroll
            for (int r = 0; r < 4; r++) acc[mf][nf][r] = 0.f;

    const int nchunk = DIM / BK;   // 32

#define STAGE(buf_, k0_) do {                                                 \
    _Pragma("unroll")                                                         \
    for (int i_ = 0; i_ < 4; i_++) {                                          \
        int idx = tid + i_ * 256;                                             \
        int row = idx >> 3;                                                   \
        int c4 = (idx & 7) << 2;                                              \
        unsigned da = uA + (buf_) * GSTG + ((unsigned)(row * 36 + c4) << 2);  \
        unsigned db = uB + (buf_) * GSTG + ((unsigned)(row * 36 + c4) << 2);  \
        const float* sa = X + (size_t)(bm + row) * DIM + (k0_) + c4;          \
        const float* sb = Wt + (size_t)(bn + row) * DIM + (k0_) + c4;         \
        asm volatile("cp.async.ca.shared.global [%0], [%1], 16;" :: "r"(da), "l"(sa)); \
        asm volatile("cp.async.ca.shared.global [%0], [%1], 16;" :: "r"(db), "l"(sb)); \
    }                                                                         \
    asm volatile("cp.async.commit_group;");                                   \
} while (0)

    STAGE(0, 0);
    STAGE(1, BK);

    for (int c = 0; c < nchunk; c++) {
        const int buf = c - (c / 3) * 3;   // c % 3
        if (c + 1 < nchunk) asm volatile("cp.async.wait_group 1;");
        else                asm volatile("cp.async.wait_group 0;");
        __syncthreads();
        if (c + 2 < nchunk) {
            const int nb = (c + 2) - ((c + 2) / 3) * 3;
            STAGE(nb, (c + 2) * BK);
        }

        const unsigned bufoff = (unsigned)buf * GSTG;
#pragma unroll
        for (int ks = 0; ks < BK; ks += 8) {
            unsigned af[4][4];
#pragma unroll
            for (int mf = 0; mf < 4; mf++)
                ldsm4(af[mf], uA + bufoff + aoff0 + ((mf * 576 + ks) << 2));
#pragma unroll
            for (int p = 0; p < 2; p++) {
                unsigned bb[4];
                ldsm4(bb, uB + bufoff + boff0 + ((p * 576 + ks) << 2));
#pragma unroll
                for (int mf = 0; mf < 4; mf++) {
                    mma_tf32(acc[mf][2 * p], af[mf], &bb[0]);
                    mma_tf32(acc[mf][2 * p + 1], af[mf], &bb[2]);
                }
            }
        }
    }

    // ---- epilogue ----
#pragma unroll
    for (int mf = 0; mf < 4; mf++) {
#pragma unroll
        for (int nf = 0; nf < 4; nf++) {
            int row0 = bm + wm * 64 + mf * 16 + g;
            int col = bn + wn * 32 + nf * 8 + 2 * t;
            float b0 = bias[col], b1 = bias[col + 1];
            float2 vtop = make_float2(acc[mf][nf][0] + b0, acc[mf][nf][1] + b1);
            float2 vbot = make_float2(acc[mf][nf][2] + b0, acc[mf][nf][3] + b1);
            if (remap == 0) {
                *(float2*)&out[(size_t)row0 * DIM + col] = vtop;
                *(float2*)&out[(size_t)(row0 + 8) * DIM + col] = vbot;
            } else {
                int h = col >> 6;
                int dh = col & 63;
#pragma unroll
                for (int rr = 0; rr < 2; rr++) {
                    int row = row0 + rr * 8;
                    int b = row >> 11;
                    int l = row & (SEQ_L - 1);
                    float2 v = rr ? vbot : vtop;
                    if (remap == 1) {
                        size_t idx = ((((size_t)b * NHEAD + h) * SEQ_L + l) << 6) + dh;
                        *(float2*)&out[idx] = v;
                    } else if (remap == 2) {
                        size_t base = (((size_t)b * NHEAD + h) * DHEAD + dh) * SEQ_L + l;
                        out[base] = uif(f2tf32(v.x));
                        out[base + SEQ_L] = uif(f2tf32(v.y));
                    } else {   // remap == 3: bf16 hi/lo split K
                        size_t idx = ((((size_t)b * NHEAD + h) * SEQ_L + l) << 6) + dh;
                        __nv_bfloat162 hp, lp;
                        hp.x = __float2bfloat16(v.x);
                        hp.y = __float2bfloat16(v.y);
                        lp.x = __float2bfloat16(v.x - __bfloat162float(hp.x));
                        lp.y = __float2bfloat16(v.y - __bfloat162float(hp.y));
                        *(__nv_bfloat162*)((__nv_bfloat16*)out + idx) = hp;
                        *(__nv_bfloat162*)((__nv_bfloat16*)out2 + idx) = lp;
                    }
                }
            }
        }
    }
}

// ---------------------------------------------------------------------------
// Tensor-core causal flash attention: bf16 hi/lo 3-pass QK, tf32 PV.
// 3-stage cp.async pipeline, ONE __syncthreads per kv-block.
// Grid (L/128, H, B), 256 threads = 8 warps x 16 q-rows.
// smem: 3 bufs x (Khi 8KB bf16 | Klo 8KB bf16 | V 16KB fp32) = 98304 B.
// ---------------------------------------------------------------------------
#define LOG2E_SCALE 0.1803368801111204f   // 0.125 * log2(e)

__global__ __launch_bounds__(256, 2) void attn_tc(
    const float* __restrict__ Q, const __nv_bfloat16* __restrict__ Kh16,
    const __nv_bfloat16* __restrict__ Kl16, const float* __restrict__ Vt,
    float* __restrict__ O)
{
    extern __shared__ float sb[];
    const unsigned usb = smem_u32(sb);

    const int qb = (gridDim.x - 1) - blockIdx.x;   // heavy CTAs first
    const int h = blockIdx.y;
    const int b = blockIdx.z;
    const int tid = threadIdx.x;
    const int w = tid >> 5, lid = tid & 31;
    const int g = lid >> 2, t = lid & 3;
    const int rowbase = qb * 128 + w * 16;

    const size_t qkOff = (size_t)(b * NHEAD + h) * SEQ_L * DHEAD;
    const size_t vtOff = (size_t)(b * NHEAD + h) * DHEAD * SEQ_L;

    // V-tile ldmatrix constants
    const int mi = lid >> 3, ri = lid & 7;
    const unsigned jbit = (unsigned)(mi & 1);
    const unsigned frow = ((unsigned)((((mi >> 1) << 3) + ri)) << 8);

    // K-tile ldmatrix base (bf16, 128B rows, 16B-chunk XOR swizzle)
    const unsigned krow = (unsigned)(lid * 128);
    const unsigned ksw = (unsigned)(lid & 7);

    // ---- Q: load, prescale, bf16 hi/lo split ONCE ----
    unsigned qha[8][2], qla[8][2];
    {
        const float* Qr0 = Q + qkOff + (size_t)(rowbase + g) * DHEAD + 2 * t;
        const float* Qr1 = Qr0 + 8 * DHEAD;
#pragma unroll
        for (int s = 0; s < 8; s++) {
            float x0 = Qr0[8 * s] * LOG2E_SCALE, x1 = Qr0[8 * s + 1] * LOG2E_SCALE;
            float y0 = Qr1[8 * s] * LOG2E_SCALE, y1 = Qr1[8 * s + 1] * LOG2E_SCALE;
            __nv_bfloat162 hx, lx, hy, ly;
            hx.x = __float2bfloat16(x0); hx.y = __float2bfloat16(x1);
            lx.x = __float2bfloat16(x0 - __bfloat162float(hx.x));
            lx.y = __float2bfloat16(x1 - __bfloat162float(hx.y));
            hy.x = __float2bfloat16(y0); hy.y = __float2bfloat16(y1);
            ly.x = __float2bfloat16(y0 - __bfloat162float(hy.x));
            ly.y = __float2bfloat16(y1 - __bfloat162float(hy.y));
            qha[s][0] = *(unsigned*)&hx; qha[s][1] = *(unsigned*)&hy;
            qla[s][0] = *(unsigned*)&lx; qla[s][1] = *(unsigned*)&ly;
        }
    }

    float oacc[8][4];
#pragma unroll
    for (int nf = 0; nf < 8; nf++)
#pragma unroll
        for (int r = 0; r < 4; r++) oacc[nf][r] = 0.f;
    float m0 = -1e30f, m1 = -1e30f, l0 = 0.f, l1 = 0.f;

    const int nkb = 2 * qb + 2;

#define LOAD_BLOCK(kb_, buf_) do {                                            \
    unsigned ub = usb + (unsigned)(buf_) * 32768u;                            \
    const __nv_bfloat16* gKh = Kh16 + qkOff + (size_t)((kb_) * 64) * 64;      \
    const __nv_bfloat16* gKl = Kl16 + qkOff + (size_t)((kb_) * 64) * 64;      \
    const float* gV = Vt + vtOff + (kb_) * 64;                                \
    _Pragma("unroll")                                                         \
    for (int r_ = 0; r_ < 2; r_++) {                                          \
        int idx = tid + r_ * 256;                                             \
        int row = idx >> 3;                                                   \
        int c = idx & 7;                                                      \
        unsigned sw = ub + (unsigned)(row * 128 + ((c ^ (row & 7)) << 4));    \
        const __nv_bfloat16* skh = gKh + row * 64 + c * 8;                    \
        const __nv_bfloat16* skl = gKl + row * 64 + c * 8;                    \
        asm volatile("cp.async.ca.shared.global [%0], [%1], 16;" :: "r"(sw), "l"(skh)); \
        asm volatile("cp.async.ca.shared.global [%0], [%1], 16;" :: "r"(sw + 8192u), "l"(skl)); \
    }                                                                         \
    _Pragma("unroll")                                                         \
    for (int r_ = 0; r_ < 4; r_++) {                                          \
        int idx = tid + r_ * 256;                                             \
        int row = idx >> 4;                                                   \
        int c4 = (idx & 15) << 2;                                             \
        unsigned sw = ub + 16384u                                             \
            + (unsigned)((((row << 6) + (c4 ^ ((row & 7) << 2)))) << 2);      \
        const float* sv = gV + (size_t)row * SEQ_L + c4;                      \
        asm volatile("cp.async.ca.shared.global [%0], [%1], 16;" :: "r"(sw), "l"(sv)); \
    }                                                                         \
    asm volatile("cp.async.commit_group;");                                   \
} while (0)

    LOAD_BLOCK(0, 0);
    LOAD_BLOCK(1, 1);

    for (int kb = 0; kb < nkb; kb++) {
        const int buf = kb - (kb / 3) * 3;   // kb % 3
        if (kb + 1 < nkb) asm volatile("cp.async.wait_group 1;");
        else              asm volatile("cp.async.wait_group 0;");
        __syncthreads();
        if (kb + 2 < nkb) {
            const int nb = (kb + 2) - ((kb + 2) / 3) * 3;
            LOAD_BLOCK(kb + 2, nb);
        }

        const int kv0 = kb * 64;
        const bool active = (kv0 <= rowbase + 15);
        if (active) {
            const unsigned uKh = usb + (unsigned)buf * 32768u;
            const unsigned uV = uKh + 16384u;

            // ---- S = Q K^T : bf16 hi/lo, 3 mmas per fragment ----
            float sacc[8][4];
#pragma unroll
            for (int nf = 0; nf < 8; nf++)
#pragma unroll
                for (int r = 0; r < 4; r++) sacc[nf][r] = 0.f;

#pragma unroll
            for (int ks = 0; ks < 8; ks++) {
                const unsigned base = uKh + krow + (((unsigned)ks ^ ksw) << 4);
                unsigned kh0[4], kh1[4], kl0[4], kl1[4];
                ldsm4(kh0, base);
                ldsm4(kh1, base + 4096u);
                ldsm4(kl0, base + 8192u);
                ldsm4(kl1, base + 12288u);
#pragma unroll
                for (int j = 0; j < 4; j++) {
                    mma_bf16(sacc[j], qha[ks], kh0[j]);
                    mma_bf16(sacc[j], qla[ks], kh0[j]);
                    mma_bf16(sacc[j], qha[ks], kl0[j]);
                    mma_bf16(sacc[j + 4], qha[ks], kh1[j]);
                    mma_bf16(sacc[j + 4], qla[ks], kh1[j]);
                    mma_bf16(sacc[j + 4], qha[ks], kl1[j]);
                }
            }

            // ---- causal mask (only near diagonal) ----
            if (kv0 + 63 > rowbase) {
#pragma unroll
                for (int nf = 0; nf < 8; nf++)
#pragma unroll
                    for (int r = 0; r < 4; r++) {
                        int col = kv0 + nf * 8 + 2 * t + (r & 1);
                        int row = rowbase + g + ((r >> 1) << 3);
                        if (col > row) sacc[nf][r] = -1e30f;
                    }
            }

            // ---- online softmax (log2 domain, raw ex2.approx) ----
            float mx0 = -1e30f, mx1 = -1e30f;
#pragma unroll
            for (int nf = 0; nf < 8; nf++) {
                mx0 = fmaxf(mx0, fmaxf(sacc[nf][0], sacc[nf][1]));
                mx1 = fmaxf(mx1, fmaxf(sacc[nf][2], sacc[nf][3]));
            }
            mx0 = fmaxf(mx0, __shfl_xor_sync(0xffffffffu, mx0, 1));
            mx0 = fmaxf(mx0, __shfl_xor_sync(0xffffffffu, mx0, 2));
            mx1 = fmaxf(mx1, __shfl_xor_sync(0xffffffffu, mx1, 1));
            mx1 = fmaxf(mx1, __shfl_xor_sync(0xffffffffu, mx1, 2));
            float mn0 = fmaxf(m0, mx0), mn1 = fmaxf(m1, mx1);
            float c0 = ex2(m0 - mn0), c1 = ex2(m1 - mn1);
            m0 = mn0; m1 = mn1;

            float s0 = 0.f, s1 = 0.f;
#pragma unroll
            for (int nf = 0; nf < 8; nf++) {
                float p0 = ex2(sacc[nf][0] - mn0);
                float p1 = ex2(sacc[nf][1] - mn0);
                float p2 = ex2(sacc[nf][2] - mn1);
                float p3 = ex2(sacc[nf][3] - mn1);
                s0 += p0 + p1; s1 += p2 + p3;
                sacc[nf][0] = p0; sacc[nf][1] = p1;
                sacc[nf][2] = p2; sacc[nf][3] = p3;
            }
            s0 += __shfl_xor_sync(0xffffffffu, s0, 1);
            s0 += __shfl_xor_sync(0xffffffffu, s0, 2);
            s1 += __shfl_xor_sync(0xffffffffu, s1, 1);
            s1 += __shfl_xor_sync(0xffffffffu, s1, 2);
            l0 = l0 * c0 + s0;
            l1 = l1 * c1 + s1;
#pragma unroll
            for (int nf = 0; nf < 8; nf++) {
                oacc[nf][0] *= c0; oacc[nf][1] *= c0;
                oacc[nf][2] *= c1; oacc[nf][3] *= c1;
            }

            // ---- O += P V (tf32; P C-layout -> A-layout via quad shuffles) ----
            const int srcA = (lid & 28) | (t >> 1);
            const int srcB = srcA + 2;
            const bool odd = (t & 1);
#pragma unroll
            for (int f = 0; f < 8; f++) {
                float v0a = __shfl_sync(0xffffffffu, sacc[f][0], srcA);
                float v1a = __shfl_sync(0xffffffffu, sacc[f][1], srcA);
                float v2a = __shfl_sync(0xffffffffu, sacc[f][2], srcA);
                float v3a = __shfl_sync(0xffffffffu, sacc[f][3], srcA);
                float v0b = __shfl_sync(0xffffffffu, sacc[f][0], srcB);
                float v1b = __shfl_sync(0xffffffffu, sacc[f][1], srcB);
                float v2b = __shfl_sync(0xffffffffu, sacc[f][2], srcB);
                float v3b = __shfl_sync(0xffffffffu, sacc[f][3], srcB);
                unsigned pa[4];
                pa[0] = f2tf32(odd ? v1a : v0a);
                pa[1] = f2tf32(odd ? v3a : v2a);
                pa[2] = f2tf32(odd ? v1b : v0b);
                pa[3] = f2tf32(odd ? v3b : v2b);
                const unsigned coff = ((((unsigned)(f << 1) + jbit) ^ (unsigned)ri) << 4);
#pragma unroll
                for (int p = 0; p < 4; p++) {
                    unsigned vv[4];
                    ldsm4(vv, uV + frow + ((unsigned)p << 12) + coff);
                    mma_tf32(oacc[2*p],     pa, &vv[0]);
                    mma_tf32(oacc[2*p + 1], pa, &vv[2]);
                }
            }
        }
    }

    // ---- write O [B, L, D], tf32-rounded (out-proj A side) ----
    float inv0 = 1.f / l0, inv1 = 1.f / l1;
    int row0 = rowbase + g;
    float* O0 = O + ((size_t)b * SEQ_L + row0) * DIM + h * DHEAD;
    float* O1 = O0 + (size_t)8 * DIM;
#pragma unroll
    for (int nf = 0; nf < 8; nf++) {
        int col = nf * 8 + 2 * t;
        *(float2*)&O0[col] = make_float2(uif(f2tf32(oacc[nf][0] * inv0)),
                                         uif(f2tf32(oacc[nf][1] * inv0)));
        *(float2*)&O1[col] = make_float2(uif(f2tf32(oacc[nf][2] * inv1)),
                                         uif(f2tf32(oacc[nf][3] * inv1)));
    }
}

// ---------------------------------------------------------------------------
extern "C" void kernel_launch(void* const* d_in, const int* in_sizes, int n_in,
                              void* d_out, int out_size)
{
    const float* q  = (const float*)d_in[0];
    const float* k  = (const float*)d_in[1];
    const float* v  = (const float*)d_in[2];
    // d_in[3] = mask (causal triu) — applied analytically, not read
    const float* Wq = (const float*)d_in[4];
    const float* bq = (const float*)d_in[5];
    const float* Wk = (const float*)d_in[6];
    const float* bk = (const float*)d_in[7];
    const float* Wv = (const float*)d_in[8];
    const float* bv = (const float*)d_in[9];
    const float* Wo = (const float*)d_in[10];
    const float* bo = (const float*)d_in[11];

    float *gxr, *gq, *gvt, *go, *gwt;
    __nv_bfloat16 *gkh, *gkl;
    cudaGetSymbolAddress((void**)&gxr, g_Xr);
    cudaGetSymbolAddress((void**)&gq, g_Q);
    cudaGetSymbolAddress((void**)&gkh, g_Kh16);
    cudaGetSymbolAddress((void**)&gkl, g_Kl16);
    cudaGetSymbolAddress((void**)&gvt, g_Vt);
    cudaGetSymbolAddress((void**)&go, g_O);
    cudaGetSymbolAddress((void**)&gwt, g_Wt);

    static int configured = 0;
    if (!configured) {
        cudaFuncSetAttribute(gemm_mma, cudaFuncAttributeMaxDynamicSharedMemorySize, GSMEM);
        cudaFuncSetAttribute(attn_tc, cudaFuncAttributeMaxDynamicSharedMemorySize, 98304);
        configured = 1;
    }

    const int NTOK = BATCH * SEQ_L * DIM;   // 4M floats per tensor

    round_inputs<<<dim3(NTOK / 1024, 3), 256>>>(q, k, v, gxr);
    transpose4<<<dim3(32, 32, 4), dim3(32, 8)>>>(Wq, Wk, Wv, Wo, gwt);

    // Fused Q/K/V projection GEMMs (grid.z = 3)
    GemmArgs qkv;
    qkv.X[0] = gxr;            qkv.X[1] = gxr + NTOK;     qkv.X[2] = gxr + 2 * NTOK;
    qkv.Wt[0] = gwt;           qkv.Wt[1] = gwt + DIM*DIM; qkv.Wt[2] = gwt + 2*DIM*DIM;
    qkv.bias[0] = bq;          qkv.bias[1] = bk;          qkv.bias[2] = bv;
    qkv.out[0] = gq;           qkv.out[1] = (float*)gkh;  qkv.out[2] = gvt;
    qkv.out2[0] = nullptr;     qkv.out2[1] = (float*)gkl; qkv.out2[2] = nullptr;
    qkv.remap[0] = 1;          qkv.remap[1] = 3;          qkv.remap[2] = 2;
    gemm_mma<<<dim3(DIM / 128, (BATCH * SEQ_L) / 128, 3), 256, GSMEM>>>(qkv);

    attn_tc<<<dim3(SEQ_L / 128, NHEAD, BATCH), 256, 98304>>>(gq, gkh, gkl, gvt, go);

    // Output projection
    GemmArgs op;
    op.X[0] = go;  op.X[1] = nullptr; op.X[2] = nullptr;
    op.Wt[0] = gwt + 3 * DIM * DIM; op.Wt[1] = nullptr; op.Wt[2] = nullptr;
    op.bias[0] = bo; op.bias[1] = nullptr; op.bias[2] = nullptr;
    op.out[0] = (float*)d_out; op.out[1] = nullptr; op.out[2] = nullptr;
    op.out2[0] = nullptr; op.out2[1] = nullptr; op.out2[2] = nullptr;
    op.remap[0] = 0; op.remap[1] = 0; op.remap[2] = 0;
    gemm_mma<<<dim3(DIM / 128, (BATCH * SEQ_L) / 128, 1), 256, GSMEM>>>(op);
}

// round 14
// speedup vs baseline: 1.1415x; 1.1415x over previous
#include <cuda_runtime.h>
#include <cuda_bf16.h>
#include <cstdint>

#define SEQ_L 2048
#define DIM 1024
#define NHEAD 16
#define DHEAD 64
#define BATCH 2

// Scratch (allocation-free)
__device__ float g_Xr[3 * BATCH * SEQ_L * DIM];        // tf32-rounded q,k,v inputs
__device__ float g_Q[BATCH * NHEAD * SEQ_L * DHEAD];
__device__ __nv_bfloat16 g_Kh16[BATCH * NHEAD * SEQ_L * DHEAD];  // K hi (bf16)
__device__ __nv_bfloat16 g_Kl16[BATCH * NHEAD * SEQ_L * DHEAD];  // K lo (bf16)
__device__ float g_Vt[BATCH * NHEAD * DHEAD * SEQ_L]; // V^T [B,H,DH,L], tf32-rounded
__device__ float g_O[BATCH * SEQ_L * DIM];            // tf32-rounded attention out
__device__ float g_Wt[4 * DIM * DIM];                 // W^T, tf32-rounded

// ---------------------------------------------------------------------------
__device__ __forceinline__ unsigned smem_u32(const void* p) {
    unsigned a;
    asm("{ .reg .u64 t; cvta.to.shared.u64 t, %1; cvt.u32.u64 %0, t; }"
        : "=r"(a) : "l"(p));
    return a;
}
__device__ __forceinline__ unsigned f2tf32(float f) {
    unsigned u;
    asm("cvt.rna.tf32.f32 %0, %1;" : "=r"(u) : "f"(f));
    return u;
}
__device__ __forceinline__ float uif(unsigned u) { return __uint_as_float(u); }
__device__ __forceinline__ float ex2(float x) {
    float y;
    asm("ex2.approx.f32 %0, %1;" : "=f"(y) : "f"(x));
    return y;
}

__device__ __forceinline__ void mma_tf32(float* c, const unsigned* a, const unsigned* b) {
    asm volatile(
        "mma.sync.aligned.m16n8k8.row.col.f32.tf32.tf32.f32 "
        "{%0,%1,%2,%3}, {%4,%5,%6,%7}, {%8,%9}, {%0,%1,%2,%3};"
        : "+f"(c[0]), "+f"(c[1]), "+f"(c[2]), "+f"(c[3])
        : "r"(a[0]), "r"(a[1]), "r"(a[2]), "r"(a[3]), "r"(b[0]), "r"(b[1]));
}
__device__ __forceinline__ void mma_bf16(float* c, const unsigned* a, unsigned b) {
    asm volatile(
        "mma.sync.aligned.m16n8k8.row.col.f32.bf16.bf16.f32 "
        "{%0,%1,%2,%3}, {%4,%5}, {%6}, {%0,%1,%2,%3};"
        : "+f"(c[0]), "+f"(c[1]), "+f"(c[2]), "+f"(c[3])
        : "r"(a[0]), "r"(a[1]), "r"(b));
}
__device__ __forceinline__ void ldsm4(unsigned* r, unsigned addr) {
    asm volatile("ldmatrix.sync.aligned.m8n8.x4.shared.b16 {%0,%1,%2,%3}, [%4];"
        : "=r"(r[0]), "=r"(r[1]), "=r"(r[2]), "=r"(r[3]) : "r"(addr));
}

// ---------------------------------------------------------------------------
// Prepass: round q,k,v inputs to tf32 into g_Xr
// ---------------------------------------------------------------------------
__global__ __launch_bounds__(256) void round_inputs(
    const float* __restrict__ q, const float* __restrict__ k,
    const float* __restrict__ v, float* __restrict__ out)
{
    const int z = blockIdx.y;
    const float* src = (z == 0) ? q : (z == 1) ? k : v;
    size_t i = ((size_t)blockIdx.x * 256 + threadIdx.x) * 4;
    float4 a = *(const float4*)(src + i);
    a.x = uif(f2tf32(a.x)); a.y = uif(f2tf32(a.y));
    a.z = uif(f2tf32(a.z)); a.w = uif(f2tf32(a.w));
    *(float4*)(out + (size_t)z * (BATCH * SEQ_L * DIM) + i) = a;
}

// ---------------------------------------------------------------------------
// Batched transpose + tf32 pre-round: g_Wt[z] = round_tf32(W_z^T)
// ---------------------------------------------------------------------------
__global__ __launch_bounds__(256) void transpose4(
    const float* __restrict__ w0, const float* __restrict__ w1,
    const float* __restrict__ w2, const float* __restrict__ w3,
    float* __restrict__ out)
{
    __shared__ float tile[32][33];
    const float* in = (blockIdx.z == 0) ? w0 : (blockIdx.z == 1) ? w1
                    : (blockIdx.z == 2) ? w2 : w3;
    float* o = out + (size_t)blockIdx.z * DIM * DIM;
    const int x = blockIdx.x * 32;
    const int y = blockIdx.y * 32;
    const int tx = threadIdx.x, ty = threadIdx.y;
#pragma unroll
    for (int i = 0; i < 32; i += 8)
        tile[ty + i][tx] = in[(size_t)(y + ty + i) * DIM + x + tx];
    __syncthreads();
#pragma unroll
    for (int i = 0; i < 32; i += 8)
        o[(size_t)(x + ty + i) * DIM + y + tx] = uif(f2tf32(tile[tx][ty + i]));
}

// ---------------------------------------------------------------------------
// tf32 mma.sync GEMM, ldmatrix fragments, pre-rounded A and B.
// CTA 128x128, BK=32, 256 threads = 8 warps of 64x32 tiles.
// Double-buffered cp.async (R12 structure — verified optimum).
// remap: 0 row-major; 1 [B,H,L,DH]; 2 [B,H,DH,L] rounded; 3 bf16 hi/lo K
// ---------------------------------------------------------------------------
#define BK 32
#define GSMEM (2 * 2 * 128 * 36 * 4)   // 73728 bytes

struct GemmArgs {
    const float* X[3];
    const float* Wt[3];
    const float* bias[3];
    float* out[3];
    float* out2[3];
    int remap[3];
};

__global__ __launch_bounds__(256, 2) void gemm_mma(GemmArgs ga)
{
    extern __shared__ float gsm[];
    const int z = blockIdx.z;
    const float* __restrict__ X = ga.X[z];
    const float* __restrict__ Wt = ga.Wt[z];
    const float* __restrict__ bias = ga.bias[z];
    float* __restrict__ out = ga.out[z];
    float* __restrict__ out2 = ga.out2[z];
    const int remap = ga.remap[z];

    const int tid = threadIdx.x;
    const int wid = tid >> 5, lid = tid & 31;
    const int wm = wid >> 2;        // 0..1 (64-row band)
    const int wn = wid & 3;         // 0..3 (32-col band)
    const int g = lid >> 2;
    const int t = lid & 3;
    const int bm = blockIdx.y * 128;
    const int bn = blockIdx.x * 128;

    const unsigned uA = smem_u32(gsm);
    const unsigned uB = uA + 36864u;

    const int mi = lid >> 3, ri = lid & 7;
    const unsigned aoff0 = ((unsigned)((wm * 64 + ((mi & 1) << 3) + ri) * 36
                                       + ((mi >> 1) << 2))) << 2;
    const unsigned boff0 = ((unsigned)((wn * 32 + ((mi >> 1) << 3) + ri) * 36
                                       + ((mi & 1) << 2))) << 2;

    float acc[4][4][4];
#pragma unroll
    for (int mf = 0; mf < 4; mf++)
#pragma unroll
        for (int nf = 0; nf < 4; nf++)
#pragma unroll
            for (int r = 0; r < 4; r++) acc[mf][nf][r] = 0.f;

    const int nchunk = DIM / BK;   // 32

#define STAGE(buf_, k0_) do {                                                 \
    _Pragma("unroll")                                                         \
    for (int i_ = 0; i_ < 4; i_++) {                                          \
        int idx = tid + i_ * 256;                                             \
        int row = idx >> 3;                                                   \
        int c4 = (idx & 7) << 2;                                              \
        unsigned da = uA + (((buf_) * 4608 + row * 36 + c4) << 2);            \
        unsigned db = uB + (((buf_) * 4608 + row * 36 + c4) << 2);            \
        const float* sa = X + (size_t)(bm + row) * DIM + (k0_) + c4;          \
        const float* sb = Wt + (size_t)(bn + row) * DIM + (k0_) + c4;         \
        asm volatile("cp.async.ca.shared.global [%0], [%1], 16;" :: "r"(da), "l"(sa)); \
        asm volatile("cp.async.ca.shared.global [%0], [%1], 16;" :: "r"(db), "l"(sb)); \
    }                                                                         \
    asm volatile("cp.async.commit_group;");                                   \
} while (0)

    STAGE(0, 0);

    for (int c = 0; c < nchunk; c++) {
        const int buf = c & 1;
        if (c + 1 < nchunk) {
            STAGE(buf ^ 1, (c + 1) * BK);
            asm volatile("cp.async.wait_group 1;");
        } else {
            asm volatile("cp.async.wait_group 0;");
        }
        __syncthreads();

        const unsigned bufoff = (unsigned)buf * 18432u;
#pragma unroll
        for (int ks = 0; ks < BK; ks += 8) {
            unsigned af[4][4];
#pragma unroll
            for (int mf = 0; mf < 4; mf++)
                ldsm4(af[mf], uA + bufoff + aoff0 + ((mf * 576 + ks) << 2));
#pragma unroll
            for (int p = 0; p < 2; p++) {
                unsigned bb[4];
                ldsm4(bb, uB + bufoff + boff0 + ((p * 576 + ks) << 2));
#pragma unroll
                for (int mf = 0; mf < 4; mf++) {
                    mma_tf32(acc[mf][2 * p], af[mf], &bb[0]);
                    mma_tf32(acc[mf][2 * p + 1], af[mf], &bb[2]);
                }
            }
        }
        __syncthreads();
    }

    // ---- epilogue ----
#pragma unroll
    for (int mf = 0; mf < 4; mf++) {
#pragma unroll
        for (int nf = 0; nf < 4; nf++) {
            int row0 = bm + wm * 64 + mf * 16 + g;
            int col = bn + wn * 32 + nf * 8 + 2 * t;
            float b0 = bias[col], b1 = bias[col + 1];
            float2 vtop = make_float2(acc[mf][nf][0] + b0, acc[mf][nf][1] + b1);
            float2 vbot = make_float2(acc[mf][nf][2] + b0, acc[mf][nf][3] + b1);
            if (remap == 0) {
                *(float2*)&out[(size_t)row0 * DIM + col] = vtop;
                *(float2*)&out[(size_t)(row0 + 8) * DIM + col] = vbot;
            } else {
                int h = col >> 6;
                int dh = col & 63;
#pragma unroll
                for (int rr = 0; rr < 2; rr++) {
                    int row = row0 + rr * 8;
                    int b = row >> 11;
                    int l = row & (SEQ_L - 1);
                    float2 v = rr ? vbot : vtop;
                    if (remap == 1) {
                        size_t idx = ((((size_t)b * NHEAD + h) * SEQ_L + l) << 6) + dh;
                        *(float2*)&out[idx] = v;
                    } else if (remap == 2) {
                        size_t base = (((size_t)b * NHEAD + h) * DHEAD + dh) * SEQ_L + l;
                        out[base] = uif(f2tf32(v.x));
                        out[base + SEQ_L] = uif(f2tf32(v.y));
                    } else {   // remap == 3: bf16 hi/lo split K
                        size_t idx = ((((size_t)b * NHEAD + h) * SEQ_L + l) << 6) + dh;
                        __nv_bfloat162 hp, lp;
                        hp.x = __float2bfloat16(v.x);
                        hp.y = __float2bfloat16(v.y);
                        lp.x = __float2bfloat16(v.x - __bfloat162float(hp.x));
                        lp.y = __float2bfloat16(v.y - __bfloat162float(hp.y));
                        *(__nv_bfloat162*)((__nv_bfloat16*)out + idx) = hp;
                        *(__nv_bfloat162*)((__nv_bfloat16*)out2 + idx) = lp;
                    }
                }
            }
        }
    }
}

// ---------------------------------------------------------------------------
// Tensor-core causal flash attention: bf16 hi/lo 3-pass QK (2x rate),
// tf32 single-pass PV. Double-buffered cp.async (R12 structure).
// Grid (L/128, H, B), 256 threads = 8 warps x 16 q-rows.
// smem: 2 bufs x (Khi 8KB bf16 | Klo 8KB bf16 | V 16KB fp32) = 65536 B.
// ---------------------------------------------------------------------------
#define LOG2E_SCALE 0.1803368801111204f   // 0.125 * log2(e)

__global__ __launch_bounds__(256, 2) void attn_tc(
    const float* __restrict__ Q, const __nv_bfloat16* __restrict__ Kh16,
    const __nv_bfloat16* __restrict__ Kl16, const float* __restrict__ Vt,
    float* __restrict__ O)
{
    extern __shared__ float sb[];
    const unsigned usb = smem_u32(sb);

    const int qb = (gridDim.x - 1) - blockIdx.x;   // heavy CTAs first
    const int h = blockIdx.y;
    const int b = blockIdx.z;
    const int tid = threadIdx.x;
    const int w = tid >> 5, lid = tid & 31;
    const int g = lid >> 2, t = lid & 3;
    const int rowbase = qb * 128 + w * 16;

    const size_t qkOff = (size_t)(b * NHEAD + h) * SEQ_L * DHEAD;
    const size_t vtOff = (size_t)(b * NHEAD + h) * DHEAD * SEQ_L;

    // V-tile ldmatrix constants
    const int mi = lid >> 3, ri = lid & 7;
    const unsigned jbit = (unsigned)(mi & 1);
    const unsigned frow = ((unsigned)((((mi >> 1) << 3) + ri)) << 8);

    // K-tile ldmatrix base (bf16, 128B rows, 16B-chunk XOR swizzle)
    const unsigned krow = (unsigned)(lid * 128);
    const unsigned ksw = (unsigned)(lid & 7);

    // ---- Q: load, prescale, bf16 hi/lo split ONCE ----
    unsigned qha[8][2], qla[8][2];
    {
        const float* Qr0 = Q + qkOff + (size_t)(rowbase + g) * DHEAD + 2 * t;
        const float* Qr1 = Qr0 + 8 * DHEAD;
#pragma unroll
        for (int s = 0; s < 8; s++) {
            float x0 = Qr0[8 * s] * LOG2E_SCALE, x1 = Qr0[8 * s + 1] * LOG2E_SCALE;
            float y0 = Qr1[8 * s] * LOG2E_SCALE, y1 = Qr1[8 * s + 1] * LOG2E_SCALE;
            __nv_bfloat162 hx, lx, hy, ly;
            hx.x = __float2bfloat16(x0); hx.y = __float2bfloat16(x1);
            lx.x = __float2bfloat16(x0 - __bfloat162float(hx.x));
            lx.y = __float2bfloat16(x1 - __bfloat162float(hx.y));
            hy.x = __float2bfloat16(y0); hy.y = __float2bfloat16(y1);
            ly.x = __float2bfloat16(y0 - __bfloat162float(hy.x));
            ly.y = __float2bfloat16(y1 - __bfloat162float(hy.y));
            qha[s][0] = *(unsigned*)&hx; qha[s][1] = *(unsigned*)&hy;
            qla[s][0] = *(unsigned*)&lx; qla[s][1] = *(unsigned*)&ly;
        }
    }

    float oacc[8][4];
#pragma unroll
    for (int nf = 0; nf < 8; nf++)
#pragma unroll
        for (int r = 0; r < 4; r++) oacc[nf][r] = 0.f;
    float m0 = -1e30f, m1 = -1e30f, l0 = 0.f, l1 = 0.f;

    const int nkb = 2 * qb + 2;

#define LOAD_BLOCK(kb_, buf_) do {                                            \
    unsigned ub = usb + (buf_) * 32768u;                                      \
    const __nv_bfloat16* gKh = Kh16 + qkOff + (size_t)((kb_) * 64) * 64;      \
    const __nv_bfloat16* gKl = Kl16 + qkOff + (size_t)((kb_) * 64) * 64;      \
    const float* gV = Vt + vtOff + (kb_) * 64;                                \
    _Pragma("unroll")                                                         \
    for (int r_ = 0; r_ < 2; r_++) {                                          \
        int idx = tid + r_ * 256;                                             \
        int row = idx >> 3;                                                   \
        int c = idx & 7;                                                      \
        unsigned sw = ub + (unsigned)(row * 128 + ((c ^ (row & 7)) << 4));    \
        const __nv_bfloat16* skh = gKh + row * 64 + c * 8;                    \
        const __nv_bfloat16* skl = gKl + row * 64 + c * 8;                    \
        asm volatile("cp.async.ca.shared.global [%0], [%1], 16;" :: "r"(sw), "l"(skh)); \
        asm volatile("cp.async.ca.shared.global [%0], [%1], 16;" :: "r"(sw + 8192u), "l"(skl)); \
    }                                                                         \
    _Pragma("unroll")                                                         \
    for (int r_ = 0; r_ < 4; r_++) {                                          \
        int idx = tid + r_ * 256;                                             \
        int row = idx >> 4;                                                   \
        int c4 = (idx & 15) << 2;                                             \
        unsigned sw = ub + 16384u                                             \
            + (unsigned)((((row << 6) + (c4 ^ ((row & 7) << 2)))) << 2);      \
        const float* sv = gV + (size_t)row * SEQ_L + c4;                      \
        asm volatile("cp.async.ca.shared.global [%0], [%1], 16;" :: "r"(sw), "l"(sv)); \
    }                                                                         \
    asm volatile("cp.async.commit_group;");                                   \
} while (0)

    LOAD_BLOCK(0, 0);

    for (int kb = 0; kb < nkb; kb++) {
        const int buf = kb & 1;
        if (kb + 1 < nkb) {
            LOAD_BLOCK(kb + 1, buf ^ 1);
            asm volatile("cp.async.wait_group 1;");
        } else {
            asm volatile("cp.async.wait_group 0;");
        }
        __syncthreads();

        const int kv0 = kb * 64;
        const bool active = (kv0 <= rowbase + 15);
        if (active) {
            const unsigned uKh = usb + (unsigned)buf * 32768u;
            const unsigned uV = uKh + 16384u;

            // ---- S = Q K^T : bf16 hi/lo, 3 mmas per fragment ----
            float sacc[8][4];
#pragma unroll
            for (int nf = 0; nf < 8; nf++)
#pragma unroll
                for (int r = 0; r < 4; r++) sacc[nf][r] = 0.f;

#pragma unroll
            for (int ks = 0; ks < 8; ks++) {
                const unsigned base = uKh + krow + (((unsigned)ks ^ ksw) << 4);
                unsigned kh0[4], kh1[4], kl0[4], kl1[4];
                ldsm4(kh0, base);
                ldsm4(kh1, base + 4096u);
                ldsm4(kl0, base + 8192u);
                ldsm4(kl1, base + 12288u);
#pragma unroll
                for (int j = 0; j < 4; j++) {
                    mma_bf16(sacc[j], qha[ks], kh0[j]);
                    mma_bf16(sacc[j], qla[ks], kh0[j]);
                    mma_bf16(sacc[j], qha[ks], kl0[j]);
                    mma_bf16(sacc[j + 4], qha[ks], kh1[j]);
                    mma_bf16(sacc[j + 4], qla[ks], kh1[j]);
                    mma_bf16(sacc[j + 4], qha[ks], kl1[j]);
                }
            }

            // ---- causal mask (only near diagonal) ----
            if (kv0 + 63 > rowbase) {
#pragma unroll
                for (int nf = 0; nf < 8; nf++)
#pragma unroll
                    for (int r = 0; r < 4; r++) {
                        int col = kv0 + nf * 8 + 2 * t + (r & 1);
                        int row = rowbase + g + ((r >> 1) << 3);
                        if (col > row) sacc[nf][r] = -1e30f;
                    }
            }

            // ---- online softmax (log2 domain, raw ex2.approx) ----
            float mx0 = -1e30f, mx1 = -1e30f;
#pragma unroll
            for (int nf = 0; nf < 8; nf++) {
                mx0 = fmaxf(mx0, fmaxf(sacc[nf][0], sacc[nf][1]));
                mx1 = fmaxf(mx1, fmaxf(sacc[nf][2], sacc[nf][3]));
            }
            mx0 = fmaxf(mx0, __shfl_xor_sync(0xffffffffu, mx0, 1));
            mx0 = fmaxf(mx0, __shfl_xor_sync(0xffffffffu, mx0, 2));
            mx1 = fmaxf(mx1, __shfl_xor_sync(0xffffffffu, mx1, 1));
            mx1 = fmaxf(mx1, __shfl_xor_sync(0xffffffffu, mx1, 2));
            float mn0 = fmaxf(m0, mx0), mn1 = fmaxf(m1, mx1);
            float c0 = ex2(m0 - mn0), c1 = ex2(m1 - mn1);
            m0 = mn0; m1 = mn1;

            float s0 = 0.f, s1 = 0.f;
#pragma unroll
            for (int nf = 0; nf < 8; nf++) {
                float p0 = ex2(sacc[nf][0] - mn0);
                float p1 = ex2(sacc[nf][1] - mn0);
                float p2 = ex2(sacc[nf][2] - mn1);
                float p3 = ex2(sacc[nf][3] - mn1);
                s0 += p0 + p1; s1 += p2 + p3;
                sacc[nf][0] = p0; sacc[nf][1] = p1;
                sacc[nf][2] = p2; sacc[nf][3] = p3;
            }
            s0 += __shfl_xor_sync(0xffffffffu, s0, 1);
            s0 += __shfl_xor_sync(0xffffffffu, s0, 2);
            s1 += __shfl_xor_sync(0xffffffffu, s1, 1);
            s1 += __shfl_xor_sync(0xffffffffu, s1, 2);
            l0 = l0 * c0 + s0;
            l1 = l1 * c1 + s1;
#pragma unroll
            for (int nf = 0; nf < 8; nf++) {
                oacc[nf][0] *= c0; oacc[nf][1] *= c0;
                oacc[nf][2] *= c1; oacc[nf][3] *= c1;
            }

            // ---- O += P V (tf32; P C-layout -> A-layout via quad shuffles) ----
            const int srcA = (lid & 28) | (t >> 1);
            const int srcB = srcA + 2;
            const bool odd = (t & 1);
#pragma unroll
            for (int f = 0; f < 8; f++) {
                float v0a = __shfl_sync(0xffffffffu, sacc[f][0], srcA);
                float v1a = __shfl_sync(0xffffffffu, sacc[f][1], srcA);
                float v2a = __shfl_sync(0xffffffffu, sacc[f][2], srcA);
                float v3a = __shfl_sync(0xffffffffu, sacc[f][3], srcA);
                float v0b = __shfl_sync(0xffffffffu, sacc[f][0], srcB);
                float v1b = __shfl_sync(0xffffffffu, sacc[f][1], srcB);
                float v2b = __shfl_sync(0xffffffffu, sacc[f][2], srcB);
                float v3b = __shfl_sync(0xffffffffu, sacc[f][3], srcB);
                unsigned pa[4];
                pa[0] = f2tf32(odd ? v1a : v0a);
                pa[1] = f2tf32(odd ? v3a : v2a);
                pa[2] = f2tf32(odd ? v1b : v0b);
                pa[3] = f2tf32(odd ? v3b : v2b);
                const unsigned coff = ((((unsigned)(f << 1) + jbit) ^ (unsigned)ri) << 4);
#pragma unroll
                for (int p = 0; p < 4; p++) {
                    unsigned vv[4];
                    ldsm4(vv, uV + frow + ((unsigned)p << 12) + coff);
                    mma_tf32(oacc[2*p],     pa, &vv[0]);
                    mma_tf32(oacc[2*p + 1], pa, &vv[2]);
                }
            }
        }
        __syncthreads();
    }

    // ---- write O [B, L, D], tf32-rounded (out-proj A side) ----
    float inv0 = 1.f / l0, inv1 = 1.f / l1;
    int row0 = rowbase + g;
    float* O0 = O + ((size_t)b * SEQ_L + row0) * DIM + h * DHEAD;
    float* O1 = O0 + (size_t)8 * DIM;
#pragma unroll
    for (int nf = 0; nf < 8; nf++) {
        int col = nf * 8 + 2 * t;
        *(float2*)&O0[col] = make_float2(uif(f2tf32(oacc[nf][0] * inv0)),
                                         uif(f2tf32(oacc[nf][1] * inv0)));
        *(float2*)&O1[col] = make_float2(uif(f2tf32(oacc[nf][2] * inv1)),
                                         uif(f2tf32(oacc[nf][3] * inv1)));
    }
}

// ---------------------------------------------------------------------------
extern "C" void kernel_launch(void* const* d_in, const int* in_sizes, int n_in,
                              void* d_out, int out_size)
{
    const float* q  = (const float*)d_in[0];
    const float* k  = (const float*)d_in[1];
    const float* v  = (const float*)d_in[2];
    // d_in[3] = mask (causal triu) — applied analytically, not read
    const float* Wq = (const float*)d_in[4];
    const float* bq = (const float*)d_in[5];
    const float* Wk = (const float*)d_in[6];
    const float* bk = (const float*)d_in[7];
    const float* Wv = (const float*)d_in[8];
    const float* bv = (const float*)d_in[9];
    const float* Wo = (const float*)d_in[10];
    const float* bo = (const float*)d_in[11];

    float *gxr, *gq, *gvt, *go, *gwt;
    __nv_bfloat16 *gkh, *gkl;
    cudaGetSymbolAddress((void**)&gxr, g_Xr);
    cudaGetSymbolAddress((void**)&gq, g_Q);
    cudaGetSymbolAddress((void**)&gkh, g_Kh16);
    cudaGetSymbolAddress((void**)&gkl, g_Kl16);
    cudaGetSymbolAddress((void**)&gvt, g_Vt);
    cudaGetSymbolAddress((void**)&go, g_O);
    cudaGetSymbolAddress((void**)&gwt, g_Wt);

    static int configured = 0;
    if (!configured) {
        cudaFuncSetAttribute(gemm_mma, cudaFuncAttributeMaxDynamicSharedMemorySize, GSMEM);
        cudaFuncSetAttribute(attn_tc, cudaFuncAttributeMaxDynamicSharedMemorySize, 65536);
        configured = 1;
    }

    const int NTOK = BATCH * SEQ_L * DIM;   // 4M floats per tensor

    round_inputs<<<dim3(NTOK / 1024, 3), 256>>>(q, k, v, gxr);
    transpose4<<<dim3(32, 32, 4), dim3(32, 8)>>>(Wq, Wk, Wv, Wo, gwt);

    // Fused Q/K/V projection GEMMs (grid.z = 3)
    GemmArgs qkv;
    qkv.X[0] = gxr;            qkv.X[1] = gxr + NTOK;     qkv.X[2] = gxr + 2 * NTOK;
    qkv.Wt[0] = gwt;           qkv.Wt[1] = gwt + DIM*DIM; qkv.Wt[2] = gwt + 2*DIM*DIM;
    qkv.bias[0] = bq;          qkv.bias[1] = bk;          qkv.bias[2] = bv;
    qkv.out[0] = gq;           qkv.out[1] = (float*)gkh;  qkv.out[2] = gvt;
    qkv.out2[0] = nullptr;     qkv.out2[1] = (float*)gkl; qkv.out2[2] = nullptr;
    qkv.remap[0] = 1;          qkv.remap[1] = 3;          qkv.remap[2] = 2;
    gemm_mma<<<dim3(DIM / 128, (BATCH * SEQ_L) / 128, 3), 256, GSMEM>>>(qkv);

    attn_tc<<<dim3(SEQ_L / 128, NHEAD, BATCH), 256, 65536>>>(gq, gkh, gkl, gvt, go);

    // Output projection
    GemmArgs op;
    op.X[0] = go;  op.X[1] = nullptr; op.X[2] = nullptr;
    op.Wt[0] = gwt + 3 * DIM * DIM; op.Wt[1] = nullptr; op.Wt[2] = nullptr;
    op.bias[0] = bo; op.bias[1] = nullptr; op.bias[2] = nullptr;
    op.out[0] = (float*)d_out; op.out[1] = nullptr; op.out[2] = nullptr;
    op.out2[0] = nullptr; op.out2[1] = nullptr; op.out2[2] = nullptr;
    op.remap[0] = 0; op.remap[1] = 0; op.remap[2] = 0;
    gemm_mma<<<dim3(DIM / 128, (BATCH * SEQ_L) / 128, 1), 256, GSMEM>>>(op);
}

// round 15
// speedup vs baseline: 1.2403x; 1.0865x over previous
#include <cuda_runtime.h>
#include <cuda_bf16.h>
#include <cstdint>

#define SEQ_L 2048
#define DIM 1024
#define NHEAD 16
#define DHEAD 64
#define BATCH 2

// Scratch (allocation-free)
__device__ float g_Xr[3 * BATCH * SEQ_L * DIM];        // tf32-rounded q,k,v inputs
__device__ float g_Q[BATCH * NHEAD * SEQ_L * DHEAD];
__device__ __nv_bfloat16 g_Kh16[BATCH * NHEAD * SEQ_L * DHEAD];  // K hi (bf16)
__device__ __nv_bfloat16 g_Kl16[BATCH * NHEAD * SEQ_L * DHEAD];  // K lo (bf16)
__device__ float g_Vt[BATCH * NHEAD * DHEAD * SEQ_L]; // V^T [B,H,DH,L], tf32-rounded
__device__ float g_O[BATCH * SEQ_L * DIM];            // tf32-rounded attention out
__device__ float g_Wt[4 * DIM * DIM];                 // W^T, tf32-rounded

// ---------------------------------------------------------------------------
__device__ __forceinline__ unsigned smem_u32(const void* p) {
    unsigned a;
    asm("{ .reg .u64 t; cvta.to.shared.u64 t, %1; cvt.u32.u64 %0, t; }"
        : "=r"(a) : "l"(p));
    return a;
}
__device__ __forceinline__ unsigned f2tf32(float f) {
    unsigned u;
    asm("cvt.rna.tf32.f32 %0, %1;" : "=r"(u) : "f"(f));
    return u;
}
__device__ __forceinline__ float uif(unsigned u) { return __uint_as_float(u); }
__device__ __forceinline__ float ex2(float x) {
    float y;
    asm("ex2.approx.f32 %0, %1;" : "=f"(y) : "f"(x));
    return y;
}

__device__ __forceinline__ void mma_tf32(float* c, const unsigned* a, const unsigned* b) {
    asm volatile(
        "mma.sync.aligned.m16n8k8.row.col.f32.tf32.tf32.f32 "
        "{%0,%1,%2,%3}, {%4,%5,%6,%7}, {%8,%9}, {%0,%1,%2,%3};"
        : "+f"(c[0]), "+f"(c[1]), "+f"(c[2]), "+f"(c[3])
        : "r"(a[0]), "r"(a[1]), "r"(a[2]), "r"(a[3]), "r"(b[0]), "r"(b[1]));
}
// m16n8k16 bf16: A = 4 regs (2 k8 fragments stacked in k), B = 2 regs
__device__ __forceinline__ void mma_bf16_k16(float* c, const unsigned* a,
                                             unsigned b0, unsigned b1) {
    asm volatile(
        "mma.sync.aligned.m16n8k16.row.col.f32.bf16.bf16.f32 "
        "{%0,%1,%2,%3}, {%4,%5,%6,%7}, {%8,%9}, {%0,%1,%2,%3};"
        : "+f"(c[0]), "+f"(c[1]), "+f"(c[2]), "+f"(c[3])
        : "r"(a[0]), "r"(a[1]), "r"(a[2]), "r"(a[3]), "r"(b0), "r"(b1));
}
__device__ __forceinline__ void ldsm4(unsigned* r, unsigned addr) {
    asm volatile("ldmatrix.sync.aligned.m8n8.x4.shared.b16 {%0,%1,%2,%3}, [%4];"
        : "=r"(r[0]), "=r"(r[1]), "=r"(r[2]), "=r"(r[3]) : "r"(addr));
}

// ---------------------------------------------------------------------------
// Prepass: round q,k,v inputs to tf32 into g_Xr
// ---------------------------------------------------------------------------
__global__ __launch_bounds__(256) void round_inputs(
    const float* __restrict__ q, const float* __restrict__ k,
    const float* __restrict__ v, float* __restrict__ out)
{
    const int z = blockIdx.y;
    const float* src = (z == 0) ? q : (z == 1) ? k : v;
    size_t i = ((size_t)blockIdx.x * 256 + threadIdx.x) * 4;
    float4 a = *(const float4*)(src + i);
    a.x = uif(f2tf32(a.x)); a.y = uif(f2tf32(a.y));
    a.z = uif(f2tf32(a.z)); a.w = uif(f2tf32(a.w));
    *(float4*)(out + (size_t)z * (BATCH * SEQ_L * DIM) + i) = a;
}

// ---------------------------------------------------------------------------
// Batched transpose + tf32 pre-round: g_Wt[z] = round_tf32(W_z^T)
// ---------------------------------------------------------------------------
__global__ __launch_bounds__(256) void transpose4(
    const float* __restrict__ w0, const float* __restrict__ w1,
    const float* __restrict__ w2, const float* __restrict__ w3,
    float* __restrict__ out)
{
    __shared__ float tile[32][33];
    const float* in = (blockIdx.z == 0) ? w0 : (blockIdx.z == 1) ? w1
                    : (blockIdx.z == 2) ? w2 : w3;
    float* o = out + (size_t)blockIdx.z * DIM * DIM;
    const int x = blockIdx.x * 32;
    const int y = blockIdx.y * 32;
    const int tx = threadIdx.x, ty = threadIdx.y;
#pragma unroll
    for (int i = 0; i < 32; i += 8)
        tile[ty + i][tx] = in[(size_t)(y + ty + i) * DIM + x + tx];
    __syncthreads();
#pragma unroll
    for (int i = 0; i < 32; i += 8)
        o[(size_t)(x + ty + i) * DIM + y + tx] = uif(f2tf32(tile[tx][ty + i]));
}

// ---------------------------------------------------------------------------
// tf32 mma.sync GEMM, ldmatrix fragments, pre-rounded A and B.
// CTA 128x128, BK=32, 256 threads = 8 warps of 64x32 tiles.
// Double-buffered cp.async (R12 structure — verified optimum).
// remap: 0 row-major; 1 [B,H,L,DH]; 2 [B,H,DH,L] rounded; 3 bf16 hi/lo K
// ---------------------------------------------------------------------------
#define BK 32
#define GSMEM (2 * 2 * 128 * 36 * 4)   // 73728 bytes

struct GemmArgs {
    const float* X[3];
    const float* Wt[3];
    const float* bias[3];
    float* out[3];
    float* out2[3];
    int remap[3];
};

__global__ __launch_bounds__(256, 2) void gemm_mma(GemmArgs ga)
{
    extern __shared__ float gsm[];
    const int z = blockIdx.z;
    const float* __restrict__ X = ga.X[z];
    const float* __restrict__ Wt = ga.Wt[z];
    const float* __restrict__ bias = ga.bias[z];
    float* __restrict__ out = ga.out[z];
    float* __restrict__ out2 = ga.out2[z];
    const int remap = ga.remap[z];

    const int tid = threadIdx.x;
    const int wid = tid >> 5, lid = tid & 31;
    const int wm = wid >> 2;        // 0..1 (64-row band)
    const int wn = wid & 3;         // 0..3 (32-col band)
    const int g = lid >> 2;
    const int t = lid & 3;
    const int bm = blockIdx.y * 128;
    const int bn = blockIdx.x * 128;

    const unsigned uA = smem_u32(gsm);
    const unsigned uB = uA + 36864u;

    const int mi = lid >> 3, ri = lid & 7;
    const unsigned aoff0 = ((unsigned)((wm * 64 + ((mi & 1) << 3) + ri) * 36
                                       + ((mi >> 1) << 2))) << 2;
    const unsigned boff0 = ((unsigned)((wn * 32 + ((mi >> 1) << 3) + ri) * 36
                                       + ((mi & 1) << 2))) << 2;

    float acc[4][4][4];
#pragma unroll
    for (int mf = 0; mf < 4; mf++)
#pragma unroll
        for (int nf = 0; nf < 4; nf++)
#pragma unroll
            for (int r = 0; r < 4; r++) acc[mf][nf][r] = 0.f;

    const int nchunk = DIM / BK;   // 32

#define STAGE(buf_, k0_) do {                                                 \
    _Pragma("unroll")                                                         \
    for (int i_ = 0; i_ < 4; i_++) {                                          \
        int idx = tid + i_ * 256;                                             \
        int row = idx >> 3;                                                   \
        int c4 = (idx & 7) << 2;                                              \
        unsigned da = uA + (((buf_) * 4608 + row * 36 + c4) << 2);            \
        unsigned db = uB + (((buf_) * 4608 + row * 36 + c4) << 2);            \
        const float* sa = X + (size_t)(bm + row) * DIM + (k0_) + c4;          \
        const float* sb = Wt + (size_t)(bn + row) * DIM + (k0_) + c4;         \
        asm volatile("cp.async.ca.shared.global [%0], [%1], 16;" :: "r"(da), "l"(sa)); \
        asm volatile("cp.async.ca.shared.global [%0], [%1], 16;" :: "r"(db), "l"(sb)); \
    }                                                                         \
    asm volatile("cp.async.commit_group;");                                   \
} while (0)

    STAGE(0, 0);

    for (int c = 0; c < nchunk; c++) {
        const int buf = c & 1;
        if (c + 1 < nchunk) {
            STAGE(buf ^ 1, (c + 1) * BK);
            asm volatile("cp.async.wait_group 1;");
        } else {
            asm volatile("cp.async.wait_group 0;");
        }
        __syncthreads();

        const unsigned bufoff = (unsigned)buf * 18432u;
#pragma unroll
        for (int ks = 0; ks < BK; ks += 8) {
            unsigned af[4][4];
#pragma unroll
            for (int mf = 0; mf < 4; mf++)
                ldsm4(af[mf], uA + bufoff + aoff0 + ((mf * 576 + ks) << 2));
#pragma unroll
            for (int p = 0; p < 2; p++) {
                unsigned bb[4];
                ldsm4(bb, uB + bufoff + boff0 + ((p * 576 + ks) << 2));
#pragma unroll
                for (int mf = 0; mf < 4; mf++) {
                    mma_tf32(acc[mf][2 * p], af[mf], &bb[0]);
                    mma_tf32(acc[mf][2 * p + 1], af[mf], &bb[2]);
                }
            }
        }
        __syncthreads();
    }

    // ---- epilogue ----
#pragma unroll
    for (int mf = 0; mf < 4; mf++) {
#pragma unroll
        for (int nf = 0; nf < 4; nf++) {
            int row0 = bm + wm * 64 + mf * 16 + g;
            int col = bn + wn * 32 + nf * 8 + 2 * t;
            float b0 = bias[col], b1 = bias[col + 1];
            float2 vtop = make_float2(acc[mf][nf][0] + b0, acc[mf][nf][1] + b1);
            float2 vbot = make_float2(acc[mf][nf][2] + b0, acc[mf][nf][3] + b1);
            if (remap == 0) {
                *(float2*)&out[(size_t)row0 * DIM + col] = vtop;
                *(float2*)&out[(size_t)(row0 + 8) * DIM + col] = vbot;
            } else {
                int h = col >> 6;
                int dh = col & 63;
#pragma unroll
                for (int rr = 0; rr < 2; rr++) {
                    int row = row0 + rr * 8;
                    int b = row >> 11;
                    int l = row & (SEQ_L - 1);
                    float2 v = rr ? vbot : vtop;
                    if (remap == 1) {
                        size_t idx = ((((size_t)b * NHEAD + h) * SEQ_L + l) << 6) + dh;
                        *(float2*)&out[idx] = v;
                    } else if (remap == 2) {
                        size_t base = (((size_t)b * NHEAD + h) * DHEAD + dh) * SEQ_L + l;
                        out[base] = uif(f2tf32(v.x));
                        out[base + SEQ_L] = uif(f2tf32(v.y));
                    } else {   // remap == 3: bf16 hi/lo split K
                        size_t idx = ((((size_t)b * NHEAD + h) * SEQ_L + l) << 6) + dh;
                        __nv_bfloat162 hp, lp;
                        hp.x = __float2bfloat16(v.x);
                        hp.y = __float2bfloat16(v.y);
                        lp.x = __float2bfloat16(v.x - __bfloat162float(hp.x));
                        lp.y = __float2bfloat16(v.y - __bfloat162float(hp.y));
                        *(__nv_bfloat162*)((__nv_bfloat16*)out + idx) = hp;
                        *(__nv_bfloat162*)((__nv_bfloat16*)out2 + idx) = lp;
                    }
                }
            }
        }
    }
}

// ---------------------------------------------------------------------------
// Tensor-core causal flash attention: bf16 hi/lo 3-pass QK with m16n8k16
// (half the MMA issues of k8), tf32 single-pass PV.
// Double-buffered cp.async (R12 structure).
// Grid (L/128, H, B), 256 threads = 8 warps x 16 q-rows.
// smem: 2 bufs x (Khi 8KB bf16 | Klo 8KB bf16 | V 16KB fp32) = 65536 B.
// ---------------------------------------------------------------------------
#define LOG2E_SCALE 0.1803368801111204f   // 0.125 * log2(e)

__global__ __launch_bounds__(256, 2) void attn_tc(
    const float* __restrict__ Q, const __nv_bfloat16* __restrict__ Kh16,
    const __nv_bfloat16* __restrict__ Kl16, const float* __restrict__ Vt,
    float* __restrict__ O)
{
    extern __shared__ float sb[];
    const unsigned usb = smem_u32(sb);

    const int qb = (gridDim.x - 1) - blockIdx.x;   // heavy CTAs first
    const int h = blockIdx.y;
    const int b = blockIdx.z;
    const int tid = threadIdx.x;
    const int w = tid >> 5, lid = tid & 31;
    const int g = lid >> 2, t = lid & 3;
    const int rowbase = qb * 128 + w * 16;

    const size_t qkOff = (size_t)(b * NHEAD + h) * SEQ_L * DHEAD;
    const size_t vtOff = (size_t)(b * NHEAD + h) * DHEAD * SEQ_L;

    // V-tile ldmatrix constants
    const int mi = lid >> 3, ri = lid & 7;
    const unsigned jbit = (unsigned)(mi & 1);
    const unsigned frow = ((unsigned)((((mi >> 1) << 3) + ri)) << 8);

    // K-tile ldmatrix base (bf16, 128B rows, 16B-chunk XOR swizzle)
    const unsigned krow = (unsigned)(lid * 128);
    const unsigned ksw = (unsigned)(lid & 7);

    // ---- Q: load, prescale, bf16 hi/lo split ONCE ----
    unsigned qha[8][2], qla[8][2];
    {
        const float* Qr0 = Q + qkOff + (size_t)(rowbase + g) * DHEAD + 2 * t;
        const float* Qr1 = Qr0 + 8 * DHEAD;
#pragma unroll
        for (int s = 0; s < 8; s++) {
            float x0 = Qr0[8 * s] * LOG2E_SCALE, x1 = Qr0[8 * s + 1] * LOG2E_SCALE;
            float y0 = Qr1[8 * s] * LOG2E_SCALE, y1 = Qr1[8 * s + 1] * LOG2E_SCALE;
            __nv_bfloat162 hx, lx, hy, ly;
            hx.x = __float2bfloat16(x0); hx.y = __float2bfloat16(x1);
            lx.x = __float2bfloat16(x0 - __bfloat162float(hx.x));
            lx.y = __float2bfloat16(x1 - __bfloat162float(hx.y));
            hy.x = __float2bfloat16(y0); hy.y = __float2bfloat16(y1);
            ly.x = __float2bfloat16(y0 - __bfloat162float(hy.x));
            ly.y = __float2bfloat16(y1 - __bfloat162float(hy.y));
            qha[s][0] = *(unsigned*)&hx; qha[s][1] = *(unsigned*)&hy;
            qla[s][0] = *(unsigned*)&lx; qla[s][1] = *(unsigned*)&ly;
        }
    }

    float oacc[8][4];
#pragma unroll
    for (int nf = 0; nf < 8; nf++)
#pragma unroll
        for (int r = 0; r < 4; r++) oacc[nf][r] = 0.f;
    float m0 = -1e30f, m1 = -1e30f, l0 = 0.f, l1 = 0.f;

    const int nkb = 2 * qb + 2;

#define LOAD_BLOCK(kb_, buf_) do {                                            \
    unsigned ub = usb + (buf_) * 32768u;                                      \
    const __nv_bfloat16* gKh = Kh16 + qkOff + (size_t)((kb_) * 64) * 64;      \
    const __nv_bfloat16* gKl = Kl16 + qkOff + (size_t)((kb_) * 64) * 64;      \
    const float* gV = Vt + vtOff + (kb_) * 64;                                \
    _Pragma("unroll")                                                         \
    for (int r_ = 0; r_ < 2; r_++) {                                          \
        int idx = tid + r_ * 256;                                             \
        int row = idx >> 3;                                                   \
        int c = idx & 7;                                                      \
        unsigned sw = ub + (unsigned)(row * 128 + ((c ^ (row & 7)) << 4));    \
        const __nv_bfloat16* skh = gKh + row * 64 + c * 8;                    \
        const __nv_bfloat16* skl = gKl + row * 64 + c * 8;                    \
        asm volatile("cp.async.ca.shared.global [%0], [%1], 16;" :: "r"(sw), "l"(skh)); \
        asm volatile("cp.async.ca.shared.global [%0], [%1], 16;" :: "r"(sw + 8192u), "l"(skl)); \
    }                                                                         \
    _Pragma("unroll")                                                         \
    for (int r_ = 0; r_ < 4; r_++) {                                          \
        int idx = tid + r_ * 256;                                             \
        int row = idx >> 4;                                                   \
        int c4 = (idx & 15) << 2;                                             \
        unsigned sw = ub + 16384u                                             \
            + (unsigned)((((row << 6) + (c4 ^ ((row & 7) << 2)))) << 2);      \
        const float* sv = gV + (size_t)row * SEQ_L + c4;                      \
        asm volatile("cp.async.ca.shared.global [%0], [%1], 16;" :: "r"(sw), "l"(sv)); \
    }                                                                         \
    asm volatile("cp.async.commit_group;");                                   \
} while (0)

    LOAD_BLOCK(0, 0);

    for (int kb = 0; kb < nkb; kb++) {
        const int buf = kb & 1;
        if (kb + 1 < nkb) {
            LOAD_BLOCK(kb + 1, buf ^ 1);
            asm volatile("cp.async.wait_group 1;");
        } else {
            asm volatile("cp.async.wait_group 0;");
        }
        __syncthreads();

        const int kv0 = kb * 64;
        const bool active = (kv0 <= rowbase + 15);
        if (active) {
            const unsigned uKh = usb + (unsigned)buf * 32768u;
            const unsigned uV = uKh + 16384u;

            // ---- S = Q K^T : bf16 hi/lo 3-pass, m16n8k16 (4 k16 chunks) ----
            float sacc[8][4];
#pragma unroll
            for (int nf = 0; nf < 8; nf++)
#pragma unroll
                for (int r = 0; r < 4; r++) sacc[nf][r] = 0.f;

#pragma unroll
            for (int c = 0; c < 4; c++) {
                const int ksA = 2 * c, ksB = 2 * c + 1;
                const unsigned baseA = uKh + krow + (((unsigned)ksA ^ ksw) << 4);
                const unsigned baseB = uKh + krow + (((unsigned)ksB ^ ksw) << 4);
                // hi/lo K fragments for both k8 halves, both kv 32-row bands
                unsigned h0a[4], h1a[4], l0a[4], l1a[4];
                unsigned h0b[4], h1b[4], l0b[4], l1b[4];
                ldsm4(h0a, baseA);            ldsm4(h0b, baseB);
                ldsm4(h1a, baseA + 4096u);    ldsm4(h1b, baseB + 4096u);
                ldsm4(l0a, baseA + 8192u);    ldsm4(l0b, baseB + 8192u);
                ldsm4(l1a, baseA + 12288u);   ldsm4(l1b, baseB + 12288u);
                // A k16 fragments: concat of k8 fragments ksA, ksB
                unsigned ah[4] = { qha[ksA][0], qha[ksA][1], qha[ksB][0], qha[ksB][1] };
                unsigned al[4] = { qla[ksA][0], qla[ksA][1], qla[ksB][0], qla[ksB][1] };
#pragma unroll
                for (int j = 0; j < 4; j++) {
                    mma_bf16_k16(sacc[j],     ah, h0a[j], h0b[j]);
                    mma_bf16_k16(sacc[j],     al, h0a[j], h0b[j]);
                    mma_bf16_k16(sacc[j],     ah, l0a[j], l0b[j]);
                    mma_bf16_k16(sacc[j + 4], ah, h1a[j], h1b[j]);
                    mma_bf16_k16(sacc[j + 4], al, h1a[j], h1b[j]);
                    mma_bf16_k16(sacc[j + 4], ah, l1a[j], l1b[j]);
                }
            }

            // ---- causal mask (only near diagonal) ----
            if (kv0 + 63 > rowbase) {
#pragma unroll
                for (int nf = 0; nf < 8; nf++)
#pragma unroll
                    for (int r = 0; r < 4; r++) {
                        int col = kv0 + nf * 8 + 2 * t + (r & 1);
                        int row = rowbase + g + ((r >> 1) << 3);
                        if (col > row) sacc[nf][r] = -1e30f;
                    }
            }

            // ---- online softmax (log2 domain, raw ex2.approx) ----
            float mx0 = -1e30f, mx1 = -1e30f;
#pragma unroll
            for (int nf = 0; nf < 8; nf++) {
                mx0 = fmaxf(mx0, fmaxf(sacc[nf][0], sacc[nf][1]));
                mx1 = fmaxf(mx1, fmaxf(sacc[nf][2], sacc[nf][3]));
            }
            mx0 = fmaxf(mx0, __shfl_xor_sync(0xffffffffu, mx0, 1));
            mx0 = fmaxf(mx0, __shfl_xor_sync(0xffffffffu, mx0, 2));
            mx1 = fmaxf(mx1, __shfl_xor_sync(0xffffffffu, mx1, 1));
            mx1 = fmaxf(mx1, __shfl_xor_sync(0xffffffffu, mx1, 2));
            float mn0 = fmaxf(m0, mx0), mn1 = fmaxf(m1, mx1);
            float c0 = ex2(m0 - mn0), c1 = ex2(m1 - mn1);
            m0 = mn0; m1 = mn1;

            float s0 = 0.f, s1 = 0.f;
#pragma unroll
            for (int nf = 0; nf < 8; nf++) {
                float p0 = ex2(sacc[nf][0] - mn0);
                float p1 = ex2(sacc[nf][1] - mn0);
                float p2 = ex2(sacc[nf][2] - mn1);
                float p3 = ex2(sacc[nf][3] - mn1);
                s0 += p0 + p1; s1 += p2 + p3;
                sacc[nf][0] = p0; sacc[nf][1] = p1;
                sacc[nf][2] = p2; sacc[nf][3] = p3;
            }
            s0 += __shfl_xor_sync(0xffffffffu, s0, 1);
            s0 += __shfl_xor_sync(0xffffffffu, s0, 2);
            s1 += __shfl_xor_sync(0xffffffffu, s1, 1);
            s1 += __shfl_xor_sync(0xffffffffu, s1, 2);
            l0 = l0 * c0 + s0;
            l1 = l1 * c1 + s1;
#pragma unroll
            for (int nf = 0; nf < 8; nf++) {
                oacc[nf][0] *= c0; oacc[nf][1] *= c0;
                oacc[nf][2] *= c1; oacc[nf][3] *= c1;
            }

            // ---- O += P V (tf32; P C-layout -> A-layout via quad shuffles) ----
            const int srcA = (lid & 28) | (t >> 1);
            const int srcB = srcA + 2;
            const bool odd = (t & 1);
#pragma unroll
            for (int f = 0; f < 8; f++) {
                float v0a = __shfl_sync(0xffffffffu, sacc[f][0], srcA);
                float v1a = __shfl_sync(0xffffffffu, sacc[f][1], srcA);
                float v2a = __shfl_sync(0xffffffffu, sacc[f][2], srcA);
                float v3a = __shfl_sync(0xffffffffu, sacc[f][3], srcA);
                float v0b = __shfl_sync(0xffffffffu, sacc[f][0], srcB);
                float v1b = __shfl_sync(0xffffffffu, sacc[f][1], srcB);
                float v2b = __shfl_sync(0xffffffffu, sacc[f][2], srcB);
                float v3b = __shfl_sync(0xffffffffu, sacc[f][3], srcB);
                unsigned pa[4];
                pa[0] = f2tf32(odd ? v1a : v0a);
                pa[1] = f2tf32(odd ? v3a : v2a);
                pa[2] = f2tf32(odd ? v1b : v0b);
                pa[3] = f2tf32(odd ? v3b : v2b);
                const unsigned coff = ((((unsigned)(f << 1) + jbit) ^ (unsigned)ri) << 4);
#pragma unroll
                for (int p = 0; p < 4; p++) {
                    unsigned vv[4];
                    ldsm4(vv, uV + frow + ((unsigned)p << 12) + coff);
                    mma_tf32(oacc[2*p],     pa, &vv[0]);
                    mma_tf32(oacc[2*p + 1], pa, &vv[2]);
                }
            }
        }
        __syncthreads();
    }

    // ---- write O [B, L, D], tf32-rounded (out-proj A side) ----
    float inv0 = 1.f / l0, inv1 = 1.f / l1;
    int row0 = rowbase + g;
    float* O0 = O + ((size_t)b * SEQ_L + row0) * DIM + h * DHEAD;
    float* O1 = O0 + (size_t)8 * DIM;
#pragma unroll
    for (int nf = 0; nf < 8; nf++) {
        int col = nf * 8 + 2 * t;
        *(float2*)&O0[col] = make_float2(uif(f2tf32(oacc[nf][0] * inv0)),
                                         uif(f2tf32(oacc[nf][1] * inv0)));
        *(float2*)&O1[col] = make_float2(uif(f2tf32(oacc[nf][2] * inv1)),
                                         uif(f2tf32(oacc[nf][3] * inv1)));
    }
}

// ---------------------------------------------------------------------------
extern "C" void kernel_launch(void* const* d_in, const int* in_sizes, int n_in,
                              void* d_out, int out_size)
{
    const float* q  = (const float*)d_in[0];
    const float* k  = (const float*)d_in[1];
    const float* v  = (const float*)d_in[2];
    // d_in[3] = mask (causal triu) — applied analytically, not read
    const float* Wq = (const float*)d_in[4];
    const float* bq = (const float*)d_in[5];
    const float* Wk = (const float*)d_in[6];
    const float* bk = (const float*)d_in[7];
    const float* Wv = (const float*)d_in[8];
    const float* bv = (const float*)d_in[9];
    const float* Wo = (const float*)d_in[10];
    const float* bo = (const float*)d_in[11];

    float *gxr, *gq, *gvt, *go, *gwt;
    __nv_bfloat16 *gkh, *gkl;
    cudaGetSymbolAddress((void**)&gxr, g_Xr);
    cudaGetSymbolAddress((void**)&gq, g_Q);
    cudaGetSymbolAddress((void**)&gkh, g_Kh16);
    cudaGetSymbolAddress((void**)&gkl, g_Kl16);
    cudaGetSymbolAddress((void**)&gvt, g_Vt);
    cudaGetSymbolAddress((void**)&go, g_O);
    cudaGetSymbolAddress((void**)&gwt, g_Wt);

    static int configured = 0;
    if (!configured) {
        cudaFuncSetAttribute(gemm_mma, cudaFuncAttributeMaxDynamicSharedMemorySize, GSMEM);
        cudaFuncSetAttribute(attn_tc, cudaFuncAttributeMaxDynamicSharedMemorySize, 65536);
        configured = 1;
    }

    const int NTOK = BATCH * SEQ_L * DIM;   // 4M floats per tensor

    round_inputs<<<dim3(NTOK / 1024, 3), 256>>>(q, k, v, gxr);
    transpose4<<<dim3(32, 32, 4), dim3(32, 8)>>>(Wq, Wk, Wv, Wo, gwt);

    // Fused Q/K/V projection GEMMs (grid.z = 3)
    GemmArgs qkv;
    qkv.X[0] = gxr;            qkv.X[1] = gxr + NTOK;     qkv.X[2] = gxr + 2 * NTOK;
    qkv.Wt[0] = gwt;           qkv.Wt[1] = gwt + DIM*DIM; qkv.Wt[2] = gwt + 2*DIM*DIM;
    qkv.bias[0] = bq;          qkv.bias[1] = bk;          qkv.bias[2] = bv;
    qkv.out[0] = gq;           qkv.out[1] = (float*)gkh;  qkv.out[2] = gvt;
    qkv.out2[0] = nullptr;     qkv.out2[1] = (float*)gkl; qkv.out2[2] = nullptr;
    qkv.remap[0] = 1;          qkv.remap[1] = 3;          qkv.remap[2] = 2;
    gemm_mma<<<dim3(DIM / 128, (BATCH * SEQ_L) / 128, 3), 256, GSMEM>>>(qkv);

    attn_tc<<<dim3(SEQ_L / 128, NHEAD, BATCH), 256, 65536>>>(gq, gkh, gkl, gvt, go);

    // Output projection
    GemmArgs op;
    op.X[0] = go;  op.X[1] = nullptr; op.X[2] = nullptr;
    op.Wt[0] = gwt + 3 * DIM * DIM; op.Wt[1] = nullptr; op.Wt[2] = nullptr;
    op.bias[0] = bo; op.bias[1] = nullptr; op.bias[2] = nullptr;
    op.out[0] = (float*)d_out; op.out[1] = nullptr; op.out[2] = nullptr;
    op.out2[0] = nullptr; op.out2[1] = nullptr; op.out2[2] = nullptr;
    op.remap[0] = 0; op.remap[1] = 0; op.remap[2] = 0;
    gemm_mma<<<dim3(DIM / 128, (BATCH * SEQ_L) / 128, 1), 256, GSMEM>>>(op);
}

// round 16
// speedup vs baseline: 1.3706x; 1.1051x over previous
#include <cuda_runtime.h>
#include <cuda_bf16.h>
#include <cuda_fp16.h>
#include <cstdint>

#define SEQ_L 2048
#define DIM 1024
#define NHEAD 16
#define DHEAD 64
#define BATCH 2

// Scratch (allocation-free)
__device__ float g_Xr[3 * BATCH * SEQ_L * DIM];        // tf32-rounded q,k,v inputs
__device__ float g_Q[BATCH * NHEAD * SEQ_L * DHEAD];
__device__ __nv_bfloat16 g_Kh16[BATCH * NHEAD * SEQ_L * DHEAD];  // K hi (bf16)
__device__ __nv_bfloat16 g_Kl16[BATCH * NHEAD * SEQ_L * DHEAD];  // K lo (bf16)
__device__ __half g_Vt[BATCH * NHEAD * DHEAD * SEQ_L]; // V^T [B,H,DH,L], fp16
__device__ float g_O[BATCH * SEQ_L * DIM];             // tf32-rounded attention out
__device__ float g_Wt[4 * DIM * DIM];                  // W^T, tf32-rounded

// ---------------------------------------------------------------------------
__device__ __forceinline__ unsigned smem_u32(const void* p) {
    unsigned a;
    asm("{ .reg .u64 t; cvta.to.shared.u64 t, %1; cvt.u32.u64 %0, t; }"
        : "=r"(a) : "l"(p));
    return a;
}
__device__ __forceinline__ unsigned f2tf32(float f) {
    unsigned u;
    asm("cvt.rna.tf32.f32 %0, %1;" : "=r"(u) : "f"(f));
    return u;
}
__device__ __forceinline__ float uif(unsigned u) { return __uint_as_float(u); }
__device__ __forceinline__ float ex2(float x) {
    float y;
    asm("ex2.approx.f32 %0, %1;" : "=f"(y) : "f"(x));
    return y;
}
// pack two fp32 -> half2 {lo=a, hi=b}
__device__ __forceinline__ unsigned pack_h2(float a, float b) {
    unsigned r;
    asm("cvt.rn.f16x2.f32 %0, %1, %2;" : "=r"(r) : "f"(b), "f"(a));
    return r;
}

__device__ __forceinline__ void mma_tf32(float* c, const unsigned* a, const unsigned* b) {
    asm volatile(
        "mma.sync.aligned.m16n8k8.row.col.f32.tf32.tf32.f32 "
        "{%0,%1,%2,%3}, {%4,%5,%6,%7}, {%8,%9}, {%0,%1,%2,%3};"
        : "+f"(c[0]), "+f"(c[1]), "+f"(c[2]), "+f"(c[3])
        : "r"(a[0]), "r"(a[1]), "r"(a[2]), "r"(a[3]), "r"(b[0]), "r"(b[1]));
}
// m16n8k16 bf16: A = 4 regs (2 k8 fragments stacked in k), B = 2 regs
__device__ __forceinline__ void mma_bf16_k16(float* c, const unsigned* a,
                                             unsigned b0, unsigned b1) {
    asm volatile(
        "mma.sync.aligned.m16n8k16.row.col.f32.bf16.bf16.f32 "
        "{%0,%1,%2,%3}, {%4,%5,%6,%7}, {%8,%9}, {%0,%1,%2,%3};"
        : "+f"(c[0]), "+f"(c[1]), "+f"(c[2]), "+f"(c[3])
        : "r"(a[0]), "r"(a[1]), "r"(a[2]), "r"(a[3]), "r"(b0), "r"(b1));
}
// m16n8k16 fp16, fp32 accum
__device__ __forceinline__ void mma_f16_k16(float* c, const unsigned* a,
                                            unsigned b0, unsigned b1) {
    asm volatile(
        "mma.sync.aligned.m16n8k16.row.col.f32.f16.f16.f32 "
        "{%0,%1,%2,%3}, {%4,%5,%6,%7}, {%8,%9}, {%0,%1,%2,%3};"
        : "+f"(c[0]), "+f"(c[1]), "+f"(c[2]), "+f"(c[3])
        : "r"(a[0]), "r"(a[1]), "r"(a[2]), "r"(a[3]), "r"(b0), "r"(b1));
}
__device__ __forceinline__ void ldsm4(unsigned* r, unsigned addr) {
    asm volatile("ldmatrix.sync.aligned.m8n8.x4.shared.b16 {%0,%1,%2,%3}, [%4];"
        : "=r"(r[0]), "=r"(r[1]), "=r"(r[2]), "=r"(r[3]) : "r"(addr));
}

// ---------------------------------------------------------------------------
// Prepass: round q,k,v inputs to tf32 into g_Xr
// ---------------------------------------------------------------------------
__global__ __launch_bounds__(256) void round_inputs(
    const float* __restrict__ q, const float* __restrict__ k,
    const float* __restrict__ v, float* __restrict__ out)
{
    const int z = blockIdx.y;
    const float* src = (z == 0) ? q : (z == 1) ? k : v;
    size_t i = ((size_t)blockIdx.x * 256 + threadIdx.x) * 4;
    float4 a = *(const float4*)(src + i);
    a.x = uif(f2tf32(a.x)); a.y = uif(f2tf32(a.y));
    a.z = uif(f2tf32(a.z)); a.w = uif(f2tf32(a.w));
    *(float4*)(out + (size_t)z * (BATCH * SEQ_L * DIM) + i) = a;
}

// ---------------------------------------------------------------------------
// Batched transpose + tf32 pre-round: g_Wt[z] = round_tf32(W_z^T)
// ---------------------------------------------------------------------------
__global__ __launch_bounds__(256) void transpose4(
    const float* __restrict__ w0, const float* __restrict__ w1,
    const float* __restrict__ w2, const float* __restrict__ w3,
    float* __restrict__ out)
{
    __shared__ float tile[32][33];
    const float* in = (blockIdx.z == 0) ? w0 : (blockIdx.z == 1) ? w1
                    : (blockIdx.z == 2) ? w2 : w3;
    float* o = out + (size_t)blockIdx.z * DIM * DIM;
    const int x = blockIdx.x * 32;
    const int y = blockIdx.y * 32;
    const int tx = threadIdx.x, ty = threadIdx.y;
#pragma unroll
    for (int i = 0; i < 32; i += 8)
        tile[ty + i][tx] = in[(size_t)(y + ty + i) * DIM + x + tx];
    __syncthreads();
#pragma unroll
    for (int i = 0; i < 32; i += 8)
        o[(size_t)(x + ty + i) * DIM + y + tx] = uif(f2tf32(tile[tx][ty + i]));
}

// ---------------------------------------------------------------------------
// tf32 mma.sync GEMM, ldmatrix fragments, pre-rounded A and B.
// CTA 128x128, BK=32, 256 threads = 8 warps of 64x32 tiles.
// Double-buffered cp.async (R12 structure — verified optimum).
// remap: 0 row-major; 1 [B,H,L,DH]; 2 [B,H,DH,L] fp16 V^T; 3 bf16 hi/lo K
// ---------------------------------------------------------------------------
#define BK 32
#define GSMEM (2 * 2 * 128 * 36 * 4)   // 73728 bytes

struct GemmArgs {
    const float* X[3];
    const float* Wt[3];
    const float* bias[3];
    float* out[3];
    float* out2[3];
    int remap[3];
};

__global__ __launch_bounds__(256, 2) void gemm_mma(GemmArgs ga)
{
    extern __shared__ float gsm[];
    const int z = blockIdx.z;
    const float* __restrict__ X = ga.X[z];
    const float* __restrict__ Wt = ga.Wt[z];
    const float* __restrict__ bias = ga.bias[z];
    float* __restrict__ out = ga.out[z];
    float* __restrict__ out2 = ga.out2[z];
    const int remap = ga.remap[z];

    const int tid = threadIdx.x;
    const int wid = tid >> 5, lid = tid & 31;
    const int wm = wid >> 2;        // 0..1 (64-row band)
    const int wn = wid & 3;         // 0..3 (32-col band)
    const int g = lid >> 2;
    const int t = lid & 3;
    const int bm = blockIdx.y * 128;
    const int bn = blockIdx.x * 128;

    const unsigned uA = smem_u32(gsm);
    const unsigned uB = uA + 36864u;

    const int mi = lid >> 3, ri = lid & 7;
    const unsigned aoff0 = ((unsigned)((wm * 64 + ((mi & 1) << 3) + ri) * 36
                                       + ((mi >> 1) << 2))) << 2;
    const unsigned boff0 = ((unsigned)((wn * 32 + ((mi >> 1) << 3) + ri) * 36
                                       + ((mi & 1) << 2))) << 2;

    float acc[4][4][4];
#pragma unroll
    for (int mf = 0; mf < 4; mf++)
#pragma unroll
        for (int nf = 0; nf < 4; nf++)
#pragma unroll
            for (int r = 0; r < 4; r++) acc[mf][nf][r] = 0.f;

    const int nchunk = DIM / BK;   // 32

#define STAGE(buf_, k0_) do {                                                 \
    _Pragma("unroll")                                                         \
    for (int i_ = 0; i_ < 4; i_++) {                                          \
        int idx = tid + i_ * 256;                                             \
        int row = idx >> 3;                                                   \
        int c4 = (idx & 7) << 2;                                              \
        unsigned da = uA + (((buf_) * 4608 + row * 36 + c4) << 2);            \
        unsigned db = uB + (((buf_) * 4608 + row * 36 + c4) << 2);            \
        const float* sa = X + (size_t)(bm + row) * DIM + (k0_) + c4;          \
        const float* sb = Wt + (size_t)(bn + row) * DIM + (k0_) + c4;         \
        asm volatile("cp.async.ca.shared.global [%0], [%1], 16;" :: "r"(da), "l"(sa)); \
        asm volatile("cp.async.ca.shared.global [%0], [%1], 16;" :: "r"(db), "l"(sb)); \
    }                                                                         \
    asm volatile("cp.async.commit_group;");                                   \
} while (0)

    STAGE(0, 0);

    for (int c = 0; c < nchunk; c++) {
        const int buf = c & 1;
        if (c + 1 < nchunk) {
            STAGE(buf ^ 1, (c + 1) * BK);
            asm volatile("cp.async.wait_group 1;");
        } else {
            asm volatile("cp.async.wait_group 0;");
        }
        __syncthreads();

        const unsigned bufoff = (unsigned)buf * 18432u;
#pragma unroll
        for (int ks = 0; ks < BK; ks += 8) {
            unsigned af[4][4];
#pragma unroll
            for (int mf = 0; mf < 4; mf++)
                ldsm4(af[mf], uA + bufoff + aoff0 + ((mf * 576 + ks) << 2));
#pragma unroll
            for (int p = 0; p < 2; p++) {
                unsigned bb[4];
                ldsm4(bb, uB + bufoff + boff0 + ((p * 576 + ks) << 2));
#pragma unroll
                for (int mf = 0; mf < 4; mf++) {
                    mma_tf32(acc[mf][2 * p], af[mf], &bb[0]);
                    mma_tf32(acc[mf][2 * p + 1], af[mf], &bb[2]);
                }
            }
        }
        __syncthreads();
    }

    // ---- epilogue ----
#pragma unroll
    for (int mf = 0; mf < 4; mf++) {
#pragma unroll
        for (int nf = 0; nf < 4; nf++) {
            int row0 = bm + wm * 64 + mf * 16 + g;
            int col = bn + wn * 32 + nf * 8 + 2 * t;
            float b0 = bias[col], b1 = bias[col + 1];
            float2 vtop = make_float2(acc[mf][nf][0] + b0, acc[mf][nf][1] + b1);
            float2 vbot = make_float2(acc[mf][nf][2] + b0, acc[mf][nf][3] + b1);
            if (remap == 0) {
                *(float2*)&out[(size_t)row0 * DIM + col] = vtop;
                *(float2*)&out[(size_t)(row0 + 8) * DIM + col] = vbot;
            } else {
                int h = col >> 6;
                int dh = col & 63;
#pragma unroll
                for (int rr = 0; rr < 2; rr++) {
                    int row = row0 + rr * 8;
                    int b = row >> 11;
                    int l = row & (SEQ_L - 1);
                    float2 v = rr ? vbot : vtop;
                    if (remap == 1) {
                        size_t idx = ((((size_t)b * NHEAD + h) * SEQ_L + l) << 6) + dh;
                        *(float2*)&out[idx] = v;
                    } else if (remap == 2) {
                        // V^T [B,H,DH,L] in fp16
                        size_t base = (((size_t)b * NHEAD + h) * DHEAD + dh) * SEQ_L + l;
                        __half* o16 = (__half*)out;
                        o16[base] = __float2half_rn(v.x);
                        o16[base + SEQ_L] = __float2half_rn(v.y);   // dh+1
                    } else {   // remap == 3: bf16 hi/lo split K
                        size_t idx = ((((size_t)b * NHEAD + h) * SEQ_L + l) << 6) + dh;
                        __nv_bfloat162 hp, lp;
                        hp.x = __float2bfloat16(v.x);
                        hp.y = __float2bfloat16(v.y);
                        lp.x = __float2bfloat16(v.x - __bfloat162float(hp.x));
                        lp.y = __float2bfloat16(v.y - __bfloat162float(hp.y));
                        *(__nv_bfloat162*)((__nv_bfloat16*)out + idx) = hp;
                        *(__nv_bfloat162*)((__nv_bfloat16*)out2 + idx) = lp;
                    }
                }
            }
        }
    }
}

// ---------------------------------------------------------------------------
// Tensor-core causal flash attention: bf16 hi/lo 3-pass QK (m16n8k16),
// fp16 m16n8k16 PV with C->A fragment reuse (NO P transpose shuffles).
// Double-buffered cp.async. Grid (L/128, H, B), 256 threads = 8 warps.
// smem: 2 bufs x (Khi 8KB | Klo 8KB | V 8KB fp16) = 49152 B.
// ---------------------------------------------------------------------------
#define LOG2E_SCALE 0.1803368801111204f   // 0.125 * log2(e)

__global__ __launch_bounds__(256, 2) void attn_tc(
    const float* __restrict__ Q, const __nv_bfloat16* __restrict__ Kh16,
    const __nv_bfloat16* __restrict__ Kl16, const __half* __restrict__ Vt,
    float* __restrict__ O)
{
    extern __shared__ float sb[];
    const unsigned usb = smem_u32(sb);

    const int qb = (gridDim.x - 1) - blockIdx.x;   // heavy CTAs first
    const int h = blockIdx.y;
    const int b = blockIdx.z;
    const int tid = threadIdx.x;
    const int w = tid >> 5, lid = tid & 31;
    const int g = lid >> 2, t = lid & 3;
    const int rowbase = qb * 128 + w * 16;

    const size_t qkOff = (size_t)(b * NHEAD + h) * SEQ_L * DHEAD;
    const size_t vtOff = (size_t)(b * NHEAD + h) * DHEAD * SEQ_L;

    // K/V-tile ldmatrix base (16-bit tiles, 128B rows, 16B-chunk XOR swizzle)
    const unsigned krow = (unsigned)(lid * 128);
    const unsigned ksw = (unsigned)(lid & 7);

    // ---- Q: load, prescale, bf16 hi/lo split ONCE ----
    unsigned qha[8][2], qla[8][2];
    {
        const float* Qr0 = Q + qkOff + (size_t)(rowbase + g) * DHEAD + 2 * t;
        const float* Qr1 = Qr0 + 8 * DHEAD;
#pragma unroll
        for (int s = 0; s < 8; s++) {
            float x0 = Qr0[8 * s] * LOG2E_SCALE, x1 = Qr0[8 * s + 1] * LOG2E_SCALE;
            float y0 = Qr1[8 * s] * LOG2E_SCALE, y1 = Qr1[8 * s + 1] * LOG2E_SCALE;
            __nv_bfloat162 hx, lx, hy, ly;
            hx.x = __float2bfloat16(x0); hx.y = __float2bfloat16(x1);
            lx.x = __float2bfloat16(x0 - __bfloat162float(hx.x));
            lx.y = __float2bfloat16(x1 - __bfloat162float(hx.y));
            hy.x = __float2bfloat16(y0); hy.y = __float2bfloat16(y1);
            ly.x = __float2bfloat16(y0 - __bfloat162float(hy.x));
            ly.y = __float2bfloat16(y1 - __bfloat162float(hy.y));
            qha[s][0] = *(unsigned*)&hx; qha[s][1] = *(unsigned*)&hy;
            qla[s][0] = *(unsigned*)&lx; qla[s][1] = *(unsigned*)&ly;
        }
    }

    float oacc[8][4];
#pragma unroll
    for (int nf = 0; nf < 8; nf++)
#pragma unroll
        for (int r = 0; r < 4; r++) oacc[nf][r] = 0.f;
    float m0 = -1e30f, m1 = -1e30f, l0 = 0.f, l1 = 0.f;

    const int nkb = 2 * qb + 2;

    // per-buf layout: Khi [0,8192) | Klo [8192,16384) | V fp16 [16384,24576)
#define LOAD_BLOCK(kb_, buf_) do {                                            \
    unsigned ub = usb + (buf_) * 24576u;                                      \
    const __nv_bfloat16* gKh = Kh16 + qkOff + (size_t)((kb_) * 64) * 64;      \
    const __nv_bfloat16* gKl = Kl16 + qkOff + (size_t)((kb_) * 64) * 64;      \
    const __half* gV = Vt + vtOff + (kb_) * 64;                               \
    _Pragma("unroll")                                                         \
    for (int r_ = 0; r_ < 2; r_++) {                                          \
        int idx = tid + r_ * 256;                                             \
        int row = idx >> 3;                                                   \
        int c = idx & 7;                                                      \
        unsigned sw = ub + (unsigned)(row * 128 + ((c ^ (row & 7)) << 4));    \
        const __nv_bfloat16* skh = gKh + row * 64 + c * 8;                    \
        const __nv_bfloat16* skl = gKl + row * 64 + c * 8;                    \
        asm volatile("cp.async.ca.shared.global [%0], [%1], 16;" :: "r"(sw), "l"(skh)); \
        asm volatile("cp.async.ca.shared.global [%0], [%1], 16;" :: "r"(sw + 8192u), "l"(skl)); \
        const __half* sv = gV + (size_t)row * SEQ_L + c * 8;                  \
        asm volatile("cp.async.ca.shared.global [%0], [%1], 16;" :: "r"(sw + 16384u), "l"(sv)); \
    }                                                                         \
    asm volatile("cp.async.commit_group;");                                   \
} while (0)

    LOAD_BLOCK(0, 0);

    for (int kb = 0; kb < nkb; kb++) {
        const int buf = kb & 1;
        if (kb + 1 < nkb) {
            LOAD_BLOCK(kb + 1, buf ^ 1);
            asm volatile("cp.async.wait_group 1;");
        } else {
            asm volatile("cp.async.wait_group 0;");
        }
        __syncthreads();

        const int kv0 = kb * 64;
        const bool active = (kv0 <= rowbase + 15);
        if (active) {
            const unsigned uKh = usb + (unsigned)buf * 24576u;
            const unsigned uV = uKh + 16384u;

            // ---- S = Q K^T : bf16 hi/lo 3-pass, m16n8k16 (4 k16 chunks) ----
            float sacc[8][4];
#pragma unroll
            for (int nf = 0; nf < 8; nf++)
#pragma unroll
                for (int r = 0; r < 4; r++) sacc[nf][r] = 0.f;

#pragma unroll
            for (int c = 0; c < 4; c++) {
                const int ksA = 2 * c, ksB = 2 * c + 1;
                const unsigned baseA = uKh + krow + (((unsigned)ksA ^ ksw) << 4);
                const unsigned baseB = uKh + krow + (((unsigned)ksB ^ ksw) << 4);
                unsigned h0a[4], h1a[4], l0a[4], l1a[4];
                unsigned h0b[4], h1b[4], l0b[4], l1b[4];
                ldsm4(h0a, baseA);            ldsm4(h0b, baseB);
                ldsm4(h1a, baseA + 4096u);    ldsm4(h1b, baseB + 4096u);
                ldsm4(l0a, baseA + 8192u);    ldsm4(l0b, baseB + 8192u);
                ldsm4(l1a, baseA + 12288u);   ldsm4(l1b, baseB + 12288u);
                unsigned ah[4] = { qha[ksA][0], qha[ksA][1], qha[ksB][0], qha[ksB][1] };
                unsigned al[4] = { qla[ksA][0], qla[ksA][1], qla[ksB][0], qla[ksB][1] };
#pragma unroll
                for (int j = 0; j < 4; j++) {
                    mma_bf16_k16(sacc[j],     ah, h0a[j], h0b[j]);
                    mma_bf16_k16(sacc[j],     al, h0a[j], h0b[j]);
                    mma_bf16_k16(sacc[j],     ah, l0a[j], l0b[j]);
                    mma_bf16_k16(sacc[j + 4], ah, h1a[j], h1b[j]);
                    mma_bf16_k16(sacc[j + 4], al, h1a[j], h1b[j]);
                    mma_bf16_k16(sacc[j + 4], ah, l1a[j], l1b[j]);
                }
            }

            // ---- causal mask (only near diagonal) ----
            if (kv0 + 63 > rowbase) {
#pragma unroll
                for (int nf = 0; nf < 8; nf++)
#pragma unroll
                    for (int r = 0; r < 4; r++) {
                        int col = kv0 + nf * 8 + 2 * t + (r & 1);
                        int row = rowbase + g + ((r >> 1) << 3);
                        if (col > row) sacc[nf][r] = -1e30f;
                    }
            }

            // ---- online softmax (log2 domain, raw ex2.approx) ----
            float mx0 = -1e30f, mx1 = -1e30f;
#pragma unroll
            for (int nf = 0; nf < 8; nf++) {
                mx0 = fmaxf(mx0, fmaxf(sacc[nf][0], sacc[nf][1]));
                mx1 = fmaxf(mx1, fmaxf(sacc[nf][2], sacc[nf][3]));
            }
            mx0 = fmaxf(mx0, __shfl_xor_sync(0xffffffffu, mx0, 1));
            mx0 = fmaxf(mx0, __shfl_xor_sync(0xffffffffu, mx0, 2));
            mx1 = fmaxf(mx1, __shfl_xor_sync(0xffffffffu, mx1, 1));
            mx1 = fmaxf(mx1, __shfl_xor_sync(0xffffffffu, mx1, 2));
            float mn0 = fmaxf(m0, mx0), mn1 = fmaxf(m1, mx1);
            float c0 = ex2(m0 - mn0), c1 = ex2(m1 - mn1);
            m0 = mn0; m1 = mn1;

            float s0 = 0.f, s1 = 0.f;
#pragma unroll
            for (int nf = 0; nf < 8; nf++) {
                float p0 = ex2(sacc[nf][0] - mn0);
                float p1 = ex2(sacc[nf][1] - mn0);
                float p2 = ex2(sacc[nf][2] - mn1);
                float p3 = ex2(sacc[nf][3] - mn1);
                s0 += p0 + p1; s1 += p2 + p3;
                sacc[nf][0] = p0; sacc[nf][1] = p1;
                sacc[nf][2] = p2; sacc[nf][3] = p3;
            }
            s0 += __shfl_xor_sync(0xffffffffu, s0, 1);
            s0 += __shfl_xor_sync(0xffffffffu, s0, 2);
            s1 += __shfl_xor_sync(0xffffffffu, s1, 1);
            s1 += __shfl_xor_sync(0xffffffffu, s1, 2);
            l0 = l0 * c0 + s0;
            l1 = l1 * c1 + s1;
#pragma unroll
            for (int nf = 0; nf < 8; nf++) {
                oacc[nf][0] *= c0; oacc[nf][1] *= c0;
                oacc[nf][2] *= c1; oacc[nf][3] *= c1;
            }

            // ---- O += P V  (fp16 m16n8k16, C-layout == A-layout: NO shuffles)
            // V tile: [d=64 rows][kv=64 cols] fp16, same swizzle as K tiles.
#pragma unroll
            for (int c = 0; c < 4; c++) {
                const int ksA = 2 * c, ksB = 2 * c + 1;
                const unsigned baseA = uV + krow + (((unsigned)ksA ^ ksw) << 4);
                const unsigned baseB = uV + krow + (((unsigned)ksB ^ ksw) << 4);
                unsigned v0a[4], v1a[4], v0b[4], v1b[4];
                ldsm4(v0a, baseA);           ldsm4(v0b, baseB);
                ldsm4(v1a, baseA + 4096u);   ldsm4(v1b, baseB + 4096u);
                unsigned pa[4];
                pa[0] = pack_h2(sacc[2 * c][0],     sacc[2 * c][1]);
                pa[1] = pack_h2(sacc[2 * c][2],     sacc[2 * c][3]);
                pa[2] = pack_h2(sacc[2 * c + 1][0], sacc[2 * c + 1][1]);
                pa[3] = pack_h2(sacc[2 * c + 1][2], sacc[2 * c + 1][3]);
#pragma unroll
                for (int j = 0; j < 4; j++) {
                    mma_f16_k16(oacc[j],     pa, v0a[j], v0b[j]);
                    mma_f16_k16(oacc[j + 4], pa, v1a[j], v1b[j]);
                }
            }
        }
        __syncthreads();
    }

    // ---- write O [B, L, D], tf32-rounded (out-proj A side) ----
    float inv0 = 1.f / l0, inv1 = 1.f / l1;
    int row0 = rowbase + g;
    float* O0 = O + ((size_t)b * SEQ_L + row0) * DIM + h * DHEAD;
    float* O1 = O0 + (size_t)8 * DIM;
#pragma unroll
    for (int nf = 0; nf < 8; nf++) {
        int col = nf * 8 + 2 * t;
        *(float2*)&O0[col] = make_float2(uif(f2tf32(oacc[nf][0] * inv0)),
                                         uif(f2tf32(oacc[nf][1] * inv0)));
        *(float2*)&O1[col] = make_float2(uif(f2tf32(oacc[nf][2] * inv1)),
                                         uif(f2tf32(oacc[nf][3] * inv1)));
    }
}

// ---------------------------------------------------------------------------
extern "C" void kernel_launch(void* const* d_in, const int* in_sizes, int n_in,
                              void* d_out, int out_size)
{
    const float* q  = (const float*)d_in[0];
    const float* k  = (const float*)d_in[1];
    const float* v  = (const float*)d_in[2];
    // d_in[3] = mask (causal triu) — applied analytically, not read
    const float* Wq = (const float*)d_in[4];
    const float* bq = (const float*)d_in[5];
    const float* Wk = (const float*)d_in[6];
    const float* bk = (const float*)d_in[7];
    const float* Wv = (const float*)d_in[8];
    const float* bv = (const float*)d_in[9];
    const float* Wo = (const float*)d_in[10];
    const float* bo = (const float*)d_in[11];

    float *gxr, *gq, *go, *gwt;
    __nv_bfloat16 *gkh, *gkl;
    __half* gvt;
    cudaGetSymbolAddress((void**)&gxr, g_Xr);
    cudaGetSymbolAddress((void**)&gq, g_Q);
    cudaGetSymbolAddress((void**)&gkh, g_Kh16);
    cudaGetSymbolAddress((void**)&gkl, g_Kl16);
    cudaGetSymbolAddress((void**)&gvt, g_Vt);
    cudaGetSymbolAddress((void**)&go, g_O);
    cudaGetSymbolAddress((void**)&gwt, g_Wt);

    static int configured = 0;
    if (!configured) {
        cudaFuncSetAttribute(gemm_mma, cudaFuncAttributeMaxDynamicSharedMemorySize, GSMEM);
        cudaFuncSetAttribute(attn_tc, cudaFuncAttributeMaxDynamicSharedMemorySize, 49152);
        configured = 1;
    }

    const int NTOK = BATCH * SEQ_L * DIM;   // 4M floats per tensor

    round_inputs<<<dim3(NTOK / 1024, 3), 256>>>(q, k, v, gxr);
    transpose4<<<dim3(32, 32, 4), dim3(32, 8)>>>(Wq, Wk, Wv, Wo, gwt);

    // Fused Q/K/V projection GEMMs (grid.z = 3)
    GemmArgs qkv;
    qkv.X[0] = gxr;            qkv.X[1] = gxr + NTOK;     qkv.X[2] = gxr + 2 * NTOK;
    qkv.Wt[0] = gwt;           qkv.Wt[1] = gwt + DIM*DIM; qkv.Wt[2] = gwt + 2*DIM*DIM;
    qkv.bias[0] = bq;          qkv.bias[1] = bk;          qkv.bias[2] = bv;
    qkv.out[0] = gq;           qkv.out[1] = (float*)gkh;  qkv.out[2] = (float*)gvt;
    qkv.out2[0] = nullptr;     qkv.out2[1] = (float*)gkl; qkv.out2[2] = nullptr;
    qkv.remap[0] = 1;          qkv.remap[1] = 3;          qkv.remap[2] = 2;
    gemm_mma<<<dim3(DIM / 128, (BATCH * SEQ_L) / 128, 3), 256, GSMEM>>>(qkv);

    attn_tc<<<dim3(SEQ_L / 128, NHEAD, BATCH), 256, 49152>>>(gq, gkh, gkl, gvt, go);

    // Output projection
    GemmArgs op;
    op.X[0] = go;  op.X[1] = nullptr; op.X[2] = nullptr;
    op.Wt[0] = gwt + 3 * DIM * DIM; op.Wt[1] = nullptr; op.Wt[2] = nullptr;
    op.bias[0] = bo; op.bias[1] = nullptr; op.bias[2] = nullptr;
    op.out[0] = (float*)d_out; op.out[1] = nullptr; op.out[2] = nullptr;
    op.out2[0] = nullptr; op.out2[1] = nullptr; op.out2[2] = nullptr;
    op.remap[0] = 0; op.remap[1] = 0; op.remap[2] = 0;
    gemm_mma<<<dim3(DIM / 128, (BATCH * SEQ_L) / 128, 1), 256, GSMEM>>>(op);
}